// round 14
// baseline (speedup 1.0000x reference)
#include <cuda_runtime.h>
#include <cuda_bf16.h>

#define NN 50000
#define EE 800000
#define DD 128
#define NH 8
#define TE 64
#define SA 168
#define WS2 136
#define SSH 24
#define SEA 40
#define XS 136
#define PS 136
#define CHUNKW (32 * WS2)

__device__ float    g_a[(size_t)EE * NH];     // exp(logit) per edge/head
__device__ float    g_agg[(size_t)NN * DD];
__device__ float    g_sum[NH];
__device__ __align__(256) __nv_bfloat16 g_wnp[256 * 128];   // aW1[0:128) | W_node
__device__ __align__(256) __nv_bfloat16 g_watt[160 * 128];  // aW1[128:160) | aW2
__device__ __align__(256) __nv_bfloat16 g_wmsg[304 * 128];  // fc1|fc2|fc3|W_sh
__device__ __align__(256) __nv_bfloat16 g_w3[128 * 8];      // aW3 bf16
__device__ __align__(256) __nv_bfloat16 g_wout[128 * 128];  // W_out bf16
__device__ __align__(256) __nv_bfloat16 g_P1[(size_t)NN * DD];
__device__ __align__(256) __nv_bfloat16 g_P2[(size_t)NN * DD];
__device__ __align__(256) __nv_bfloat16 g_XW[(size_t)NN * DD];

__device__ __forceinline__ float siluf(float x) {
    float t;
    asm("tanh.approx.f32 %0, %1;" : "=f"(t) : "f"(x * 0.5f));
    return 0.5f * x * (1.f + t);
}
__device__ __forceinline__ void ldsm4(unsigned (&r)[4], unsigned addr) {
    asm volatile("ldmatrix.sync.aligned.m8n8.x4.shared.b16 {%0,%1,%2,%3}, [%4];"
                 : "=r"(r[0]), "=r"(r[1]), "=r"(r[2]), "=r"(r[3]) : "r"(addr));
}
__device__ __forceinline__ void ldsm4t(unsigned* r, unsigned addr) {
    asm volatile("ldmatrix.sync.aligned.m8n8.x4.trans.shared.b16 {%0,%1,%2,%3}, [%4];"
                 : "=r"(r[0]), "=r"(r[1]), "=r"(r[2]), "=r"(r[3]) : "r"(addr));
}
__device__ __forceinline__ void ldsm2t(unsigned& r0, unsigned& r1, unsigned addr) {
    asm volatile("ldmatrix.sync.aligned.m8n8.x2.trans.shared.b16 {%0,%1}, [%2];"
                 : "=r"(r0), "=r"(r1) : "r"(addr));
}
__device__ __forceinline__ void mma16(float (&d)[4], const unsigned (&a)[4],
                                      unsigned b0, unsigned b1) {
    asm volatile(
        "mma.sync.aligned.m16n8k16.row.col.f32.bf16.bf16.f32 "
        "{%0,%1,%2,%3}, {%4,%5,%6,%7}, {%8,%9}, {%0,%1,%2,%3};\n"
        : "+f"(d[0]), "+f"(d[1]), "+f"(d[2]), "+f"(d[3])
        : "r"(a[0]), "r"(a[1]), "r"(a[2]), "r"(a[3]), "r"(b0), "r"(b1));
}
__device__ __forceinline__ unsigned cvta(const void* p) {
    return (unsigned)__cvta_generic_to_shared(p);
}
__device__ __forceinline__ unsigned packbf(float a, float b) {
    __nv_bfloat162 v = __floats2bfloat162_rn(a, b);
    return *(unsigned*)&v;
}
__device__ __forceinline__ void redv2(float* p, float a, float b) {
    asm volatile("red.global.add.v2.f32 [%0], {%1, %2};"
                 :: "l"(p), "f"(a), "f"(b) : "memory");
}
__device__ __forceinline__ void clr16(float (&acc)[16][4]) {
#pragma unroll
    for (int i = 0; i < 16; i++)
#pragma unroll
        for (int j = 0; j < 4; j++) acc[i][j] = 0.f;
}
__device__ __forceinline__ void clr8(float (&acc)[8][4]) {
#pragma unroll
    for (int i = 0; i < 8; i++)
#pragma unroll
        for (int j = 0; j < 4; j++) acc[i][j] = 0.f;
}

__device__ __forceinline__ void prefetch_chunk(__nv_bfloat16* sbuf,
        const __nv_bfloat16* __restrict__ gsrc, int nrows, int tid, int nthr)
{
    for (int idx = tid; idx < nrows * 16; idx += nthr) {
        int row = idx >> 4, seg = idx & 15;
        unsigned d = cvta(sbuf + row * WS2) + seg * 16;
        const char* s = (const char*)(gsrc + (size_t)row * 128) + seg * 16;
        asm volatile("cp.async.cg.shared.global [%0], [%1], 16;" :: "r"(d), "l"(s));
    }
    asm volatile("cp.async.commit_group;" ::: "memory");
}
__device__ __forceinline__ void commit_empty() {
    asm volatile("cp.async.commit_group;" ::: "memory");
}
__device__ __forceinline__ void wait1() {
    asm volatile("cp.async.wait_group 1;" ::: "memory");
}
__device__ __forceinline__ int bufi(int ci) { return ci % 3; }

// ===== 4-warp chain tile: warp = 16 rows x 128 cols, acc[16][4] =====
template<int NK>
__device__ __forceinline__ void cmma_s(const __nv_bfloat16* sW,
        const __nv_bfloat16* sA, int lda, float (&acc)[16][4],
        int lrow, int lcol8, int mr0)
{
#pragma unroll
    for (int ks = 0; ks < NK / 16; ks++) {
        unsigned a[4];
        ldsm4(a, cvta(sA + (mr0 + lrow) * lda + ks * 16 + lcol8));
#pragma unroll
        for (int np = 0; np < 8; np++) {
            unsigned bb[4];
            ldsm4t(bb, cvta(sW + (ks * 16 + lrow) * WS2 + np * 16 + lcol8));
            mma16(acc[2 * np], a, bb[0], bb[1]);
            mma16(acc[2 * np + 1], a, bb[2], bb[3]);
        }
    }
}
__device__ __forceinline__ void cmma_r(const __nv_bfloat16* sW,
        const unsigned* aP, int cc, float (&acc)[16][4], int lrow, int lcol8)
{
#pragma unroll
    for (int ks = 0; ks < 2; ks++) {
        const int kg = 2 * cc + ks;
        unsigned a[4] = {aP[4 * kg], aP[4 * kg + 1], aP[4 * kg + 2], aP[4 * kg + 3]};
#pragma unroll
        for (int np = 0; np < 8; np++) {
            unsigned bb[4];
            ldsm4t(bb, cvta(sW + (ks * 16 + lrow) * WS2 + np * 16 + lcol8));
            mma16(acc[2 * np], a, bb[0], bb[1]);
            mma16(acc[2 * np + 1], a, bb[2], bb[3]);
        }
    }
}
// one K=32 chunk, A from shared; triple-buffered, ONE sync per chunk
__device__ __forceinline__ int pipe_s32(int ci, int nchTot, int lastRows,
        const __nv_bfloat16* __restrict__ gw, __nv_bfloat16* sWb,
        const __nv_bfloat16* sA, int lda, float (&acc)[16][4],
        int tid, int lrow, int lcol8, int mr0)
{
    int nxt = ci + 1;
    if (nxt < nchTot)
        prefetch_chunk(sWb + bufi(nxt) * CHUNKW, gw + (size_t)nxt * 4096,
                       (nxt == nchTot - 1) ? lastRows : 32, tid, 128);
    else commit_empty();
    wait1();
    __syncthreads();
    cmma_s<32>(sWb + bufi(ci) * CHUNKW, sA, lda, acc, lrow, lcol8, mr0);
    return ci + 1;
}
// nc K=32 chunks, A from registers
__device__ __forceinline__ int pipe_r(int ci, int nc, int nchTot, int lastRows,
        const __nv_bfloat16* __restrict__ gw, __nv_bfloat16* sWb,
        const unsigned* aP, float (&acc)[16][4],
        int tid, int lrow, int lcol8)
{
    for (int cc = 0; cc < nc; cc++) {
        int nxt = ci + 1;
        if (nxt < nchTot)
            prefetch_chunk(sWb + bufi(nxt) * CHUNKW, gw + (size_t)nxt * 4096,
                           (nxt == nchTot - 1) ? lastRows : 32, tid, 128);
        else commit_empty();
        wait1();
        __syncthreads();
        cmma_r(sWb + bufi(ci) * CHUNKW, aP, cc, acc, lrow, lcol8);
        ci++;
    }
    return ci;
}

// ===== 8-warp helpers (nodeproj + k_node; 256 threads, acc[8][4]) =====
template<int NK>
__device__ __forceinline__ void chunk_mma8(const __nv_bfloat16* sW,
        const __nv_bfloat16* sA, int lda, int kc, float (&acc)[8][4],
        int lrow, int lcol8, int mr0, int nc0)
{
#pragma unroll
    for (int k0 = 0; k0 < NK; k0 += 16) {
        unsigned a[4];
        ldsm4(a, cvta(sA + (mr0 + lrow) * lda + kc + k0 + lcol8));
        unsigned b[16];
#pragma unroll
        for (int np = 0; np < 4; np++)
            ldsm4t(b + np * 4, cvta(sW + (k0 + lrow) * WS2 + nc0 + np * 16 + lcol8));
#pragma unroll
        for (int nt = 0; nt < 8; nt++)
            mma16(acc[nt], a, b[(nt >> 1) * 4 + (nt & 1) * 2],
                              b[(nt >> 1) * 4 + (nt & 1) * 2 + 1]);
    }
}
__device__ __forceinline__ int pipe8(int ci, int nc, int nchTot, int lastRows,
        const __nv_bfloat16* __restrict__ gw, __nv_bfloat16* sWb,
        const __nv_bfloat16* sA, int lda, float (&acc)[8][4],
        int tid, int lrow, int lcol8, int mr0, int nc0)
{
    for (int cc = 0; cc < nc; cc++) {
        int nxt = ci + 1;
        if (nxt < nchTot)
            prefetch_chunk(sWb + bufi(nxt) * CHUNKW, gw + (size_t)nxt * 4096,
                           (nxt == nchTot - 1) ? lastRows : 32, tid, 256);
        else commit_empty();
        wait1();
        __syncthreads();
        chunk_mma8<32>(sWb + bufi(ci) * CHUNKW, sA, lda, cc * 32, acc,
                       lrow, lcol8, mr0, nc0);
        ci++;
    }
    return ci;
}

// ---------------- weight packing ----------------
__global__ void k_prep(const float* __restrict__ W_node, const float* __restrict__ fc1,
                       const float* __restrict__ fc2, const float* __restrict__ fc3,
                       const float* __restrict__ W_sh, const float* __restrict__ aW1,
                       const float* __restrict__ aW2, const float* __restrict__ aW3,
                       const float* __restrict__ W_out)
{
    int i = blockIdx.x * blockDim.x + threadIdx.x;
    int row = i >> 7, col = i & 127;
    if (i < 256 * 128) {
        float v = (row < 128) ? aW1[row * 128 + col] : W_node[(row - 128) * 128 + col];
        g_wnp[i] = __float2bfloat16(v);
    }
    if (i < 160 * 128) {
        float v = (row < 32) ? aW1[(128 + row) * 128 + col] : aW2[(row - 32) * 128 + col];
        g_watt[i] = __float2bfloat16(v);
    }
    if (i < 304 * 128) {
        float v;
        if (row < 32)       v = fc1[row * 128 + col];
        else if (row < 160) v = fc2[(row - 32) * 128 + col];
        else if (row < 288) v = fc3[(row - 160) * 128 + col];
        else                v = W_sh[(row - 288) * 128 + col];
        g_wmsg[i] = __float2bfloat16(v);
    }
    if (i < 128 * 128) g_wout[i] = __float2bfloat16(W_out[i]);
    if (i < 128 * 8) g_w3[i] = __float2bfloat16(aW3[i]);
}

__global__ void k_init()
{
    int i = blockIdx.x * blockDim.x + threadIdx.x;
    int stride = gridDim.x * blockDim.x;
    float4 z = make_float4(0.f, 0.f, 0.f, 0.f);
    for (int j = i; j < NN * DD / 4; j += stride) ((float4*)g_agg)[j] = z;
    if (i < NH) g_sum[i] = 0.f;
}

// ---------------- node projections: P1, P2, XW ----------------
__global__ void __launch_bounds__(256, 3)
k_nodeproj(const float* __restrict__ nf)
{
    extern __shared__ char smem[];
    __nv_bfloat16* s_A  = (__nv_bfloat16*)smem;             // 21504
    __nv_bfloat16* s_Wb = (__nv_bfloat16*)(smem + 21504);   // 26112

    const int tid = threadIdx.x, lane = tid & 31, wid = tid >> 5;
    const int r = lane >> 2, c = lane & 3;
    const int lrow = lane & 15, lcol8 = (lane >> 1) & 8;
    const int mr0 = (wid & 3) * 16, nc0 = (wid >> 2) * 64;
    const int n0 = blockIdx.x * 64;

    prefetch_chunk(s_Wb, g_wnp, 32, tid, 256);

#pragma unroll
    for (int i = 0; i < 8; i++) {
        int rr = wid * 8 + i;
        int n = n0 + rr; if (n >= NN) n = NN - 1;
        const float4 v = *(const float4*)(nf + (size_t)n * DD + lane * 4);
        *(__nv_bfloat162*)(s_A + rr * SA + lane * 4)     = __floats2bfloat162_rn(v.x, v.y);
        *(__nv_bfloat162*)(s_A + rr * SA + lane * 4 + 2) = __floats2bfloat162_rn(v.z, v.w);
    }

    float acc[8][4];
    clr8(acc);
    int ci = pipe8(0, 2, 8, 32, g_wnp, s_Wb, s_A, SA, acc, tid, lrow, lcol8, mr0, nc0);
#pragma unroll
    for (int nt = 0; nt < 8; nt++) {
        int col = nc0 + nt * 8 + 2 * c;
        int row0 = n0 + mr0 + r, row1 = row0 + 8;
        if (row0 < NN) *(__nv_bfloat162*)(g_P1 + (size_t)row0 * DD + col) =
            __floats2bfloat162_rn(acc[nt][0], acc[nt][1]);
        if (row1 < NN) *(__nv_bfloat162*)(g_P1 + (size_t)row1 * DD + col) =
            __floats2bfloat162_rn(acc[nt][2], acc[nt][3]);
    }
    clr8(acc);
    ci = pipe8(ci, 2, 8, 32, g_wnp, s_Wb, s_A, SA, acc, tid, lrow, lcol8, mr0, nc0);
#pragma unroll
    for (int nt = 0; nt < 8; nt++) {
        int col = nc0 + nt * 8 + 2 * c;
        int row0 = n0 + mr0 + r, row1 = row0 + 8;
        if (row0 < NN) *(__nv_bfloat162*)(g_P2 + (size_t)row0 * DD + col) =
            __floats2bfloat162_rn(acc[nt][0], acc[nt][1]);
        if (row1 < NN) *(__nv_bfloat162*)(g_P2 + (size_t)row1 * DD + col) =
            __floats2bfloat162_rn(acc[nt][2], acc[nt][3]);
    }
    clr8(acc);
    ci = pipe8(ci, 4, 8, 32, g_wnp, s_Wb, s_A, SA, acc, tid, lrow, lcol8, mr0, nc0);
#pragma unroll
    for (int nt = 0; nt < 8; nt++) {
        int col = nc0 + nt * 8 + 2 * c;
        int row0 = n0 + mr0 + r, row1 = row0 + 8;
        if (row0 < NN) *(__nv_bfloat162*)(g_XW + (size_t)row0 * DD + col) =
            __floats2bfloat162_rn(acc[nt][0], acc[nt][1]);
        if (row1 < NN) *(__nv_bfloat162*)(g_XW + (size_t)row1 * DD + col) =
            __floats2bfloat162_rn(acc[nt][2], acc[nt][3]);
    }
}

// ---------------- K1: attention -> exp(logits) + fused per-head sums ----------------
// smem: s_Wb 26112 | s_ea 5120 | s_pd 17408 | s_w3 2048 | bias 1024 | ab3 32 |
//       hsum 32 | src 256 | dst 256 => 52288
__global__ void __launch_bounds__(128, 4)
k_att(const float* __restrict__ edge_attr,
      const float* __restrict__ ab1, const float* __restrict__ ab2,
      const float* __restrict__ ab3, const int* __restrict__ edge_index)
{
    extern __shared__ char smem[];
    __nv_bfloat16* s_Wb = (__nv_bfloat16*)smem;                 // 26112
    __nv_bfloat16* s_ea = (__nv_bfloat16*)(smem + 26112);       // 5120
    __nv_bfloat16* s_pd = (__nv_bfloat16*)(smem + 31232);       // 17408
    __nv_bfloat16* s_w3 = (__nv_bfloat16*)(smem + 48640);       // 2048
    float* s_bias = (float*)(smem + 50688);                     // 1024
    float* s_ab3  = (float*)(smem + 51712);                     // 32
    float* s_hsum = (float*)(smem + 51744);                     // 32
    int*   s_src  = (int*)(smem + 51776);                       // 256
    int*   s_dst  = (int*)(smem + 52032);                       // 256

    const int tid = threadIdx.x, lane = tid & 31, wid = tid >> 5;
    const int r = lane >> 2, c = lane & 3;
    const int lrow = lane & 15, lcol8 = (lane >> 1) & 8;
    const int mr0 = wid * 16;
    const int e0 = blockIdx.x * TE;

    prefetch_chunk(s_Wb, g_watt, 32, tid, 128);

    if (tid < TE) {
        s_src[tid] = edge_index[e0 + tid];
        s_dst[tid] = edge_index[EE + e0 + tid];
    }
    s_bias[tid]       = ab1[tid];
    s_bias[128 + tid] = ab2[tid];
    if (tid < NH) { s_ab3[tid] = ab3[tid]; s_hsum[tid] = 0.f; }
    ((uint4*)s_w3)[tid] = ((const uint4*)g_w3)[tid];

    for (int idx = tid; idx < TE * 8; idx += 128) {
        int rr = idx >> 3, cc = (idx & 7) << 2;
        const float4 v = *(const float4*)(edge_attr + (size_t)(e0 + rr) * 32 + cc);
        *(__nv_bfloat162*)(s_ea + rr * SEA + cc)     = __floats2bfloat162_rn(v.x, v.y);
        *(__nv_bfloat162*)(s_ea + rr * SEA + cc + 2) = __floats2bfloat162_rn(v.z, v.w);
    }
    __syncthreads();
    // gather P1[src] + P2[dst] -> s_pd (warp-private rows)
#pragma unroll
    for (int i = 0; i < 16; i++) {
        int rr = mr0 + i;
        int s = s_src[rr], d = s_dst[rr];
        __nv_bfloat162 a0 = *(const __nv_bfloat162*)(g_P1 + (size_t)s * DD + lane * 4);
        __nv_bfloat162 a1 = *(const __nv_bfloat162*)(g_P1 + (size_t)s * DD + lane * 4 + 2);
        __nv_bfloat162 b0 = *(const __nv_bfloat162*)(g_P2 + (size_t)d * DD + lane * 4);
        __nv_bfloat162 b1 = *(const __nv_bfloat162*)(g_P2 + (size_t)d * DD + lane * 4 + 2);
        float2 f0 = __bfloat1622float2(a0), f1 = __bfloat1622float2(b0);
        float2 f2 = __bfloat1622float2(a1), f3 = __bfloat1622float2(b1);
        *(__nv_bfloat162*)(s_pd + rr * PS + lane * 4) =
            __floats2bfloat162_rn(f0.x + f1.x, f0.y + f1.y);
        *(__nv_bfloat162*)(s_pd + rr * PS + lane * 4 + 2) =
            __floats2bfloat162_rn(f2.x + f3.x, f2.y + f3.y);
    }

    float acc[16][4];
    unsigned aP[32];
    // layer1: ea @ aW1_e (chunk 0)
    clr16(acc);
    int ci = pipe_s32(0, 5, 32, g_watt, s_Wb, s_ea, SEA, acc, tid, lrow, lcol8, mr0);
#pragma unroll
    for (int nt = 0; nt < 16; nt++) {
        int col = 8 * nt + 2 * c;
        float b0 = s_bias[col], b1 = s_bias[col + 1];
        float2 p0 = __bfloat1622float2(*(const __nv_bfloat162*)(s_pd + (mr0 + r) * PS + col));
        float2 p1 = __bfloat1622float2(*(const __nv_bfloat162*)(s_pd + (mr0 + r + 8) * PS + col));
        aP[2 * nt]     = packbf(siluf(acc[nt][0] + p0.x + b0), siluf(acc[nt][1] + p0.y + b1));
        aP[2 * nt + 1] = packbf(siluf(acc[nt][2] + p1.x + b0), siluf(acc[nt][3] + p1.y + b1));
    }
    // layer2: aW2 (chunks 1-4), A from registers
    clr16(acc);
    ci = pipe_r(ci, 4, 5, 32, g_watt, s_Wb, aP, acc, tid, lrow, lcol8);
#pragma unroll
    for (int nt = 0; nt < 16; nt++) {
        int col = 8 * nt + 2 * c;
        float b0 = s_bias[128 + col], b1 = s_bias[128 + col + 1];
        aP[2 * nt]     = packbf(siluf(acc[nt][0] + b0), siluf(acc[nt][1] + b1));
        aP[2 * nt + 1] = packbf(siluf(acc[nt][2] + b0), siluf(acc[nt][3] + b1));
    }
    // logit layer: K=128 from registers, B = s_w3 (n=8)
    float la[4] = {0.f, 0.f, 0.f, 0.f};
#pragma unroll
    for (int ks = 0; ks < 8; ks++) {
        unsigned b0, b1;
        ldsm2t(b0, b1, cvta(s_w3 + (16 * ks + lrow) * 8));
        unsigned av[4] = {aP[4 * ks], aP[4 * ks + 1], aP[4 * ks + 2], aP[4 * ks + 3]};
        mma16(la, av, b0, b1);
    }
    float h0 = s_ab3[2 * c], h1 = s_ab3[2 * c + 1];
    float e00 = __expf(la[0] + h0), e01 = __expf(la[1] + h1);
    float e10 = __expf(la[2] + h0), e11 = __expf(la[3] + h1);
    *(float2*)(g_a + (size_t)(e0 + mr0 + r) * NH + 2 * c)     = make_float2(e00, e01);
    *(float2*)(g_a + (size_t)(e0 + mr0 + r + 8) * NH + 2 * c) = make_float2(e10, e11);

    // fused per-head sums: reduce over r (lanes stride 4), then smem, then global
    float s0 = e00 + e10, s1 = e01 + e11;
#pragma unroll
    for (int o = 4; o < 32; o <<= 1) {
        s0 += __shfl_xor_sync(0xffffffffu, s0, o);
        s1 += __shfl_xor_sync(0xffffffffu, s1, o);
    }
    if (lane < 4) {
        atomicAdd(&s_hsum[2 * lane], s0);
        atomicAdd(&s_hsum[2 * lane + 1], s1);
    }
    __syncthreads();
    if (tid < NH) atomicAdd(&g_sum[tid], s_hsum[tid]);
}

// ---------------- K3: message MLP + fragment-direct weighted scatter ----------------
// smem: s_Wb 26112 | s_ea 5120 | s_x 17408 | s_sh 3072 | bias 1536 | wt 256 |
//       ish 32 | src 256 | dst 256 => 54048
__global__ void __launch_bounds__(128, 4)
k_msg(const float* __restrict__ edge_attr, const float* __restrict__ edge_sh,
      const float* __restrict__ b1, const float* __restrict__ b2,
      const float* __restrict__ b3v, const int* __restrict__ edge_index)
{
    extern __shared__ char smem[];
    __nv_bfloat16* s_Wb = (__nv_bfloat16*)smem;                 // 26112
    __nv_bfloat16* s_ea = (__nv_bfloat16*)(smem + 26112);       // 5120
    __nv_bfloat16* s_x  = (__nv_bfloat16*)(smem + 31232);       // 17408
    __nv_bfloat16* s_sh = (__nv_bfloat16*)(smem + 48640);       // 3072
    float* s_bias = (float*)(smem + 51712);                     // 1536
    float* s_wt   = (float*)(smem + 53248);                     // 256
    float* s_ish  = (float*)(smem + 53504);                     // 32
    int*   s_src  = (int*)(smem + 53536);                       // 256
    int*   s_dst  = (int*)(smem + 53792);                       // 256

    const int tid = threadIdx.x, lane = tid & 31, wid = tid >> 5;
    const int r = lane >> 2, c = lane & 3;
    const int lrow = lane & 15, lcol8 = (lane >> 1) & 8;
    const int mr0 = wid * 16;
    const int e0 = blockIdx.x * TE;

    prefetch_chunk(s_Wb, g_wmsg, 32, tid, 128);

    if (tid < TE) {
        s_src[tid] = edge_index[e0 + tid];
        s_dst[tid] = edge_index[EE + e0 + tid];
    }
    s_bias[tid]       = b1[tid];
    s_bias[128 + tid] = b2[tid];
    s_bias[256 + tid] = b3v[tid];
    if (tid < NH) s_ish[tid] = 0.125f / g_sum[tid];
    for (int idx = tid; idx < TE * 4; idx += 128) {
        int rr = idx >> 2, cc = (idx & 3) << 2;
        const float4 v = *(const float4*)(edge_sh + (size_t)(e0 + rr) * 16 + cc);
        *(__nv_bfloat162*)(s_sh + rr * SSH + cc)     = __floats2bfloat162_rn(v.x, v.y);
        *(__nv_bfloat162*)(s_sh + rr * SSH + cc + 2) = __floats2bfloat162_rn(v.z, v.w);
    }
    for (int idx = tid; idx < TE * 8; idx += 128) {
        int rr = idx >> 3, cc = (idx & 7) << 2;
        const float4 v = *(const float4*)(edge_attr + (size_t)(e0 + rr) * 32 + cc);
        *(__nv_bfloat162*)(s_ea + rr * SEA + cc)     = __floats2bfloat162_rn(v.x, v.y);
        *(__nv_bfloat162*)(s_ea + rr * SEA + cc + 2) = __floats2bfloat162_rn(v.z, v.w);
    }
    __syncthreads();
    if (tid < TE) {   // per-edge softmax-mean weight
        const float4 ev0 = *(const float4*)(g_a + (size_t)(e0 + tid) * NH);
        const float4 ev1 = *(const float4*)(g_a + (size_t)(e0 + tid) * NH + 4);
        s_wt[tid] = ev0.x * s_ish[0] + ev0.y * s_ish[1] + ev0.z * s_ish[2] + ev0.w * s_ish[3]
                  + ev1.x * s_ish[4] + ev1.y * s_ish[5] + ev1.z * s_ish[6] + ev1.w * s_ish[7];
    }
    // gather XW[src] -> s_x (warp-private rows)
#pragma unroll
    for (int i = 0; i < 16; i++) {
        int rr = mr0 + i;
        const uint2 v = *(const uint2*)(g_XW + (size_t)s_src[rr] * DD + lane * 4);
        *(uint2*)(s_x + rr * XS + lane * 4) = v;
    }

    float acc[16][4];
    unsigned aP[32];
    // fc1 (chunk 0, K=32, A = s_ea)
    clr16(acc);
    int ci = pipe_s32(0, 10, 16, g_wmsg, s_Wb, s_ea, SEA, acc, tid, lrow, lcol8, mr0);
#pragma unroll
    for (int nt = 0; nt < 16; nt++) {
        int col = 8 * nt + 2 * c;
        float b0 = s_bias[col], b1v = s_bias[col + 1];
        aP[2 * nt]     = packbf(siluf(acc[nt][0] + b0), siluf(acc[nt][1] + b1v));
        aP[2 * nt + 1] = packbf(siluf(acc[nt][2] + b0), siluf(acc[nt][3] + b1v));
    }
    // fc2 (chunks 1-4)
    clr16(acc);
    ci = pipe_r(ci, 4, 10, 16, g_wmsg, s_Wb, aP, acc, tid, lrow, lcol8);
#pragma unroll
    for (int nt = 0; nt < 16; nt++) {
        int col = 8 * nt + 2 * c;
        float b0 = s_bias[128 + col], b1v = s_bias[128 + col + 1];
        aP[2 * nt]     = packbf(siluf(acc[nt][0] + b0), siluf(acc[nt][1] + b1v));
        aP[2 * nt + 1] = packbf(siluf(acc[nt][2] + b0), siluf(acc[nt][3] + b1v));
    }
    // fc3 (chunks 5-8) -> scale (fp32 in acc)
    clr16(acc);
    ci = pipe_r(ci, 4, 10, 16, g_wmsg, s_Wb, aP, acc, tid, lrow, lcol8);
#pragma unroll
    for (int nt = 0; nt < 16; nt++) {
        int col = 8 * nt + 2 * c;
        acc[nt][0] += s_bias[256 + col];
        acc[nt][1] += s_bias[256 + col + 1];
        acc[nt][2] += s_bias[256 + col];
        acc[nt][3] += s_bias[256 + col + 1];
    }
    // prod = xw * scale -> bf16 back into s_x (frag-owned slots)
#pragma unroll
    for (int ks = 0; ks < 8; ks++) {
        unsigned xw[4];
        ldsm4(xw, cvta(s_x + (mr0 + lrow) * XS + 16 * ks + lcol8));
        float2 f;
        f = __bfloat1622float2(*(__nv_bfloat162*)&xw[0]);
        *(unsigned*)(s_x + (mr0 + r) * XS + 16 * ks + 2 * c) =
            packbf(f.x * acc[2 * ks][0], f.y * acc[2 * ks][1]);
        f = __bfloat1622float2(*(__nv_bfloat162*)&xw[1]);
        *(unsigned*)(s_x + (mr0 + r + 8) * XS + 16 * ks + 2 * c) =
            packbf(f.x * acc[2 * ks][2], f.y * acc[2 * ks][3]);
        f = __bfloat1622float2(*(__nv_bfloat162*)&xw[2]);
        *(unsigned*)(s_x + (mr0 + r) * XS + 16 * ks + 8 + 2 * c) =
            packbf(f.x * acc[2 * ks + 1][0], f.y * acc[2 * ks + 1][1]);
        f = __bfloat1622float2(*(__nv_bfloat162*)&xw[3]);
        *(unsigned*)(s_x + (mr0 + r + 8) * XS + 16 * ks + 8 + 2 * c) =
            packbf(f.x * acc[2 * ks + 1][2], f.y * acc[2 * ks + 1][3]);
    }
    // shp = edge_sh @ W_sh (chunk 9, 16 rows, A = s_sh)
    clr16(acc);
    commit_empty();
    wait1();
    __syncthreads();
    cmma_s<16>(s_Wb + bufi(ci) * CHUNKW, s_sh, SSH, acc, lrow, lcol8, mr0);
    // msg = silu(prod + shp) * wt  -> red.v2 DIRECT from fragments to g_agg[dst]
    float w0 = s_wt[mr0 + r], w1 = s_wt[mr0 + r + 8];
    float* p0base = g_agg + (size_t)s_dst[mr0 + r] * DD;
    float* p1base = g_agg + (size_t)s_dst[mr0 + r + 8] * DD;
#pragma unroll
    for (int nt = 0; nt < 16; nt++) {
        int col = 8 * nt + 2 * c;
        float2 p0 = __bfloat1622float2(*(__nv_bfloat162*)(s_x + (mr0 + r) * XS + col));
        float2 p1 = __bfloat1622float2(*(__nv_bfloat162*)(s_x + (mr0 + r + 8) * XS + col));
        redv2(p0base + col, siluf(p0.x + acc[nt][0]) * w0, siluf(p0.y + acc[nt][1]) * w0);
        redv2(p1base + col, siluf(p1.x + acc[nt][2]) * w1, siluf(p1.y + acc[nt][3]) * w1);
    }
}

// ---------------- K4: out = LN(nf + agg @ W_out), MMA version ----------------
// smem: s_A 21504 | s_Wb 26112 | s_red 1024 => 48640
__global__ void __launch_bounds__(256, 3)
k_node(const float* __restrict__ nf, float* __restrict__ out)
{
    extern __shared__ char smem[];
    __nv_bfloat16* s_A  = (__nv_bfloat16*)smem;             // 21504
    __nv_bfloat16* s_Wb = (__nv_bfloat16*)(smem + 21504);   // 26112
    float* s_red = (float*)(smem + 47616);                  // 64 rows x 2 halves x 2

    const int tid = threadIdx.x, lane = tid & 31, wid = tid >> 5;
    const int r = lane >> 2, c = lane & 3;
    const int lrow = lane & 15, lcol8 = (lane >> 1) & 8;
    const int mr0 = (wid & 3) * 16, nc0 = (wid >> 2) * 64;
    const int half = wid >> 2;
    const int n0 = blockIdx.x * 64;

    prefetch_chunk(s_Wb, g_wout, 32, tid, 256);

#pragma unroll
    for (int i = 0; i < 8; i++) {
        int rr = wid * 8 + i;
        int n = n0 + rr; if (n >= NN) n = NN - 1;
        const float4 v = *(const float4*)(g_agg + (size_t)n * DD + lane * 4);
        *(__nv_bfloat162*)(s_A + rr * SA + lane * 4)     = __floats2bfloat162_rn(v.x, v.y);
        *(__nv_bfloat162*)(s_A + rr * SA + lane * 4 + 2) = __floats2bfloat162_rn(v.z, v.w);
    }

    float acc[8][4];
    clr8(acc);
    pipe8(0, 4, 4, 32, g_wout, s_Wb, s_A, SA, acc, tid, lrow, lcol8, mr0, nc0);

    const int lr0 = mr0 + r, lr1 = lr0 + 8;
    int row0 = n0 + lr0, row1 = n0 + lr1;
    int cr0 = row0 < NN ? row0 : NN - 1;
    int cr1 = row1 < NN ? row1 : NN - 1;
    float sum0 = 0.f, sq0 = 0.f, sum1 = 0.f, sq1 = 0.f;
#pragma unroll
    for (int nt = 0; nt < 8; nt++) {
        int col = nc0 + nt * 8 + 2 * c;
        const float2 x0 = *(const float2*)(nf + (size_t)cr0 * DD + col);
        const float2 x1 = *(const float2*)(nf + (size_t)cr1 * DD + col);
        acc[nt][0] += x0.x; acc[nt][1] += x0.y;
        acc[nt][2] += x1.x; acc[nt][3] += x1.y;
        sum0 += acc[nt][0] + acc[nt][1];
        sq0  += acc[nt][0] * acc[nt][0] + acc[nt][1] * acc[nt][1];
        sum1 += acc[nt][2] + acc[nt][3];
        sq1  += acc[nt][2] * acc[nt][2] + acc[nt][3] * acc[nt][3];
    }
    // quad reduce over c (lanes r*4+c)
#pragma unroll
    for (int o = 1; o < 4; o <<= 1) {
        sum0 += __shfl_xor_sync(0xffffffffu, sum0, o);
        sq0  += __shfl_xor_sync(0xffffffffu, sq0,  o);
        sum1 += __shfl_xor_sync(0xffffffffu, sum1, o);
        sq1  += __shfl_xor_sync(0xffffffffu, sq1,  o);
    }
    if (c == 0) {
        s_red[(lr0 * 2 + half) * 2 + 0] = sum0;
        s_red[(lr0 * 2 + half) * 2 + 1] = sq0;
        s_red[(lr1 * 2 + half) * 2 + 0] = sum1;
        s_red[(lr1 * 2 + half) * 2 + 1] = sq1;
    }
    __syncthreads();
    float ts0 = s_red[(lr0 * 2 + 0) * 2 + 0] + s_red[(lr0 * 2 + 1) * 2 + 0];
    float tq0 = s_red[(lr0 * 2 + 0) * 2 + 1] + s_red[(lr0 * 2 + 1) * 2 + 1];
    float ts1 = s_red[(lr1 * 2 + 0) * 2 + 0] + s_red[(lr1 * 2 + 1) * 2 + 0];
    float tq1 = s_red[(lr1 * 2 + 0) * 2 + 1] + s_red[(lr1 * 2 + 1) * 2 + 1];
    float mu0 = ts0 * (1.f / 128.f);
    float mu1 = ts1 * (1.f / 128.f);
    float rs0 = rsqrtf(tq0 * (1.f / 128.f) - mu0 * mu0 + 1e-5f);
    float rs1 = rsqrtf(tq1 * (1.f / 128.f) - mu1 * mu1 + 1e-5f);
#pragma unroll
    for (int nt = 0; nt < 8; nt++) {
        int col = nc0 + nt * 8 + 2 * c;
        if (row0 < NN)
            *(float2*)(out + (size_t)row0 * DD + col) =
                make_float2((acc[nt][0] - mu0) * rs0, (acc[nt][1] - mu0) * rs0);
        if (row1 < NN)
            *(float2*)(out + (size_t)row1 * DD + col) =
                make_float2((acc[nt][2] - mu1) * rs1, (acc[nt][3] - mu1) * rs1);
    }
}

extern "C" void kernel_launch(void* const* d_in, const int* in_sizes, int n_in,
                              void* d_out, int out_size)
{
    const float* nf        = (const float*)d_in[0];
    const float* edge_attr = (const float*)d_in[1];
    const float* edge_sh   = (const float*)d_in[2];
    const float* W_node    = (const float*)d_in[3];
    const float* fc1 = (const float*)d_in[4];
    const float* b1  = (const float*)d_in[5];
    const float* fc2 = (const float*)d_in[6];
    const float* b2  = (const float*)d_in[7];
    const float* fc3 = (const float*)d_in[8];
    const float* b3  = (const float*)d_in[9];
    const float* W_sh = (const float*)d_in[10];
    const float* aW1 = (const float*)d_in[11];
    const float* ab1 = (const float*)d_in[12];
    const float* aW2 = (const float*)d_in[13];
    const float* ab2 = (const float*)d_in[14];
    const float* aW3 = (const float*)d_in[15];
    const float* ab3 = (const float*)d_in[16];
    const float* W_out = (const float*)d_in[17];
    const int* edge_index = (const int*)d_in[18];
    float* out = (float*)d_out;

    const int SMEM_NP   = 47616;
    const int SMEM_ATT  = 52288;
    const int SMEM_MSG  = 54048;
    const int SMEM_NODE = 48640;
    cudaFuncSetAttribute(k_nodeproj, cudaFuncAttributeMaxDynamicSharedMemorySize, SMEM_NP);
    cudaFuncSetAttribute(k_att,  cudaFuncAttributeMaxDynamicSharedMemorySize, SMEM_ATT);
    cudaFuncSetAttribute(k_msg,  cudaFuncAttributeMaxDynamicSharedMemorySize, SMEM_MSG);
    cudaFuncSetAttribute(k_node, cudaFuncAttributeMaxDynamicSharedMemorySize, SMEM_NODE);

    k_prep<<<152, 256>>>(W_node, fc1, fc2, fc3, W_sh, aW1, aW2, aW3, W_out);
    k_init<<<2048, 256>>>();
    k_nodeproj<<<(NN + 63) / 64, 256, SMEM_NP>>>(nf);
    k_att<<<EE / TE, 128, SMEM_ATT>>>(edge_attr, ab1, ab2, ab3, edge_index);
    k_msg<<<EE / TE, 128, SMEM_MSG>>>(edge_attr, edge_sh, b1, b2, b3, edge_index);
    k_node<<<(NN + 63) / 64, 256, SMEM_NODE>>>(nf, out);
}

// round 15
// speedup vs baseline: 1.2744x; 1.2744x over previous
#include <cuda_runtime.h>
#include <cuda_bf16.h>

#define NN 50000
#define EE 800000
#define DD 128
#define NH 8
#define TE 64
#define SA 168
#define WS2 136
#define SSH 24
#define SEA 40
#define XS 136
#define PS 136
#define CHUNKW (32 * WS2)

__device__ __nv_bfloat16 g_a[(size_t)EE * NH];   // exp(logit) per edge/head (bf16)
__device__ float    g_agg[(size_t)NN * DD];
__device__ float    g_sum[NH];
__device__ __align__(256) __nv_bfloat16 g_wnp[256 * 128];   // aW1[0:128) | W_node
__device__ __align__(256) __nv_bfloat16 g_watt[160 * 128];  // aW1[128:160) | aW2
__device__ __align__(256) __nv_bfloat16 g_wmsg[304 * 128];  // fc1|fc2|fc3|W_sh
__device__ __align__(256) __nv_bfloat16 g_w3[128 * 8];      // aW3 bf16
__device__ __align__(256) __nv_bfloat16 g_wout[128 * 128];  // W_out bf16
__device__ __align__(256) __nv_bfloat16 g_P1[(size_t)NN * DD];
__device__ __align__(256) __nv_bfloat16 g_P2[(size_t)NN * DD];
__device__ __align__(256) __nv_bfloat16 g_XW[(size_t)NN * DD];

__device__ __forceinline__ float siluf(float x) {
    float t;
    asm("tanh.approx.f32 %0, %1;" : "=f"(t) : "f"(x * 0.5f));
    return 0.5f * x * (1.f + t);
}
__device__ __forceinline__ void ldsm4(unsigned (&r)[4], unsigned addr) {
    asm volatile("ldmatrix.sync.aligned.m8n8.x4.shared.b16 {%0,%1,%2,%3}, [%4];"
                 : "=r"(r[0]), "=r"(r[1]), "=r"(r[2]), "=r"(r[3]) : "r"(addr));
}
__device__ __forceinline__ void ldsm4t(unsigned* r, unsigned addr) {
    asm volatile("ldmatrix.sync.aligned.m8n8.x4.trans.shared.b16 {%0,%1,%2,%3}, [%4];"
                 : "=r"(r[0]), "=r"(r[1]), "=r"(r[2]), "=r"(r[3]) : "r"(addr));
}
__device__ __forceinline__ void ldsm2t(unsigned& r0, unsigned& r1, unsigned addr) {
    asm volatile("ldmatrix.sync.aligned.m8n8.x2.trans.shared.b16 {%0,%1}, [%2];"
                 : "=r"(r0), "=r"(r1) : "r"(addr));
}
__device__ __forceinline__ void mma16(float (&d)[4], const unsigned (&a)[4],
                                      unsigned b0, unsigned b1) {
    asm volatile(
        "mma.sync.aligned.m16n8k16.row.col.f32.bf16.bf16.f32 "
        "{%0,%1,%2,%3}, {%4,%5,%6,%7}, {%8,%9}, {%0,%1,%2,%3};\n"
        : "+f"(d[0]), "+f"(d[1]), "+f"(d[2]), "+f"(d[3])
        : "r"(a[0]), "r"(a[1]), "r"(a[2]), "r"(a[3]), "r"(b0), "r"(b1));
}
__device__ __forceinline__ unsigned cvta(const void* p) {
    return (unsigned)__cvta_generic_to_shared(p);
}
__device__ __forceinline__ unsigned packbf(float a, float b) {
    __nv_bfloat162 v = __floats2bfloat162_rn(a, b);
    return *(unsigned*)&v;
}
__device__ __forceinline__ void clr16(float (&acc)[16][4]) {
#pragma unroll
    for (int i = 0; i < 16; i++)
#pragma unroll
        for (int j = 0; j < 4; j++) acc[i][j] = 0.f;
}
__device__ __forceinline__ void clr8(float (&acc)[8][4]) {
#pragma unroll
    for (int i = 0; i < 8; i++)
#pragma unroll
        for (int j = 0; j < 4; j++) acc[i][j] = 0.f;
}

__device__ __forceinline__ void prefetch_chunk(__nv_bfloat16* sbuf,
        const __nv_bfloat16* __restrict__ gsrc, int nrows, int tid, int nthr)
{
    for (int idx = tid; idx < nrows * 16; idx += nthr) {
        int row = idx >> 4, seg = idx & 15;
        unsigned d = cvta(sbuf + row * WS2) + seg * 16;
        const char* s = (const char*)(gsrc + (size_t)row * 128) + seg * 16;
        asm volatile("cp.async.cg.shared.global [%0], [%1], 16;" :: "r"(d), "l"(s));
    }
    asm volatile("cp.async.commit_group;" ::: "memory");
}
__device__ __forceinline__ void commit_empty() {
    asm volatile("cp.async.commit_group;" ::: "memory");
}
__device__ __forceinline__ void wait1() {
    asm volatile("cp.async.wait_group 1;" ::: "memory");
}
__device__ __forceinline__ int bufi(int ci) { return ci % 3; }

// ===== 4-warp chain tile: warp = 16 rows x 128 cols, acc[16][4] =====
template<int NK>
__device__ __forceinline__ void cmma_s(const __nv_bfloat16* sW,
        const __nv_bfloat16* sA, int lda, float (&acc)[16][4],
        int lrow, int lcol8, int mr0)
{
#pragma unroll
    for (int ks = 0; ks < NK / 16; ks++) {
        unsigned a[4];
        ldsm4(a, cvta(sA + (mr0 + lrow) * lda + ks * 16 + lcol8));
#pragma unroll
        for (int np = 0; np < 8; np++) {
            unsigned bb[4];
            ldsm4t(bb, cvta(sW + (ks * 16 + lrow) * WS2 + np * 16 + lcol8));
            mma16(acc[2 * np], a, bb[0], bb[1]);
            mma16(acc[2 * np + 1], a, bb[2], bb[3]);
        }
    }
}
__device__ __forceinline__ void cmma_r(const __nv_bfloat16* sW,
        const unsigned* aP, int cc, float (&acc)[16][4], int lrow, int lcol8)
{
#pragma unroll
    for (int ks = 0; ks < 2; ks++) {
        const int kg = 2 * cc + ks;
        unsigned a[4] = {aP[4 * kg], aP[4 * kg + 1], aP[4 * kg + 2], aP[4 * kg + 3]};
#pragma unroll
        for (int np = 0; np < 8; np++) {
            unsigned bb[4];
            ldsm4t(bb, cvta(sW + (ks * 16 + lrow) * WS2 + np * 16 + lcol8));
            mma16(acc[2 * np], a, bb[0], bb[1]);
            mma16(acc[2 * np + 1], a, bb[2], bb[3]);
        }
    }
}
// one K=32 chunk, A from shared; triple-buffered, ONE sync per chunk
__device__ __forceinline__ int pipe_s32(int ci, int nchTot, int lastRows,
        const __nv_bfloat16* __restrict__ gw, __nv_bfloat16* sWb,
        const __nv_bfloat16* sA, int lda, float (&acc)[16][4],
        int tid, int lrow, int lcol8, int mr0)
{
    int nxt = ci + 1;
    if (nxt < nchTot)
        prefetch_chunk(sWb + bufi(nxt) * CHUNKW, gw + (size_t)nxt * 4096,
                       (nxt == nchTot - 1) ? lastRows : 32, tid, 128);
    else commit_empty();
    wait1();
    __syncthreads();
    cmma_s<32>(sWb + bufi(ci) * CHUNKW, sA, lda, acc, lrow, lcol8, mr0);
    return ci + 1;
}
// nc K=32 chunks, A from registers
__device__ __forceinline__ int pipe_r(int ci, int nc, int nchTot, int lastRows,
        const __nv_bfloat16* __restrict__ gw, __nv_bfloat16* sWb,
        const unsigned* aP, float (&acc)[16][4],
        int tid, int lrow, int lcol8)
{
    for (int cc = 0; cc < nc; cc++) {
        int nxt = ci + 1;
        if (nxt < nchTot)
            prefetch_chunk(sWb + bufi(nxt) * CHUNKW, gw + (size_t)nxt * 4096,
                           (nxt == nchTot - 1) ? lastRows : 32, tid, 128);
        else commit_empty();
        wait1();
        __syncthreads();
        cmma_r(sWb + bufi(ci) * CHUNKW, aP, cc, acc, lrow, lcol8);
        ci++;
    }
    return ci;
}

// ===== 8-warp helpers (nodeproj + k_node; 256 threads, acc[8][4]) =====
template<int NK>
__device__ __forceinline__ void chunk_mma8(const __nv_bfloat16* sW,
        const __nv_bfloat16* sA, int lda, int kc, float (&acc)[8][4],
        int lrow, int lcol8, int mr0, int nc0)
{
#pragma unroll
    for (int k0 = 0; k0 < NK; k0 += 16) {
        unsigned a[4];
        ldsm4(a, cvta(sA + (mr0 + lrow) * lda + kc + k0 + lcol8));
        unsigned b[16];
#pragma unroll
        for (int np = 0; np < 4; np++)
            ldsm4t(b + np * 4, cvta(sW + (k0 + lrow) * WS2 + nc0 + np * 16 + lcol8));
#pragma unroll
        for (int nt = 0; nt < 8; nt++)
            mma16(acc[nt], a, b[(nt >> 1) * 4 + (nt & 1) * 2],
                              b[(nt >> 1) * 4 + (nt & 1) * 2 + 1]);
    }
}
__device__ __forceinline__ int pipe8(int ci, int nc, int nchTot, int lastRows,
        const __nv_bfloat16* __restrict__ gw, __nv_bfloat16* sWb,
        const __nv_bfloat16* sA, int lda, float (&acc)[8][4],
        int tid, int lrow, int lcol8, int mr0, int nc0)
{
    for (int cc = 0; cc < nc; cc++) {
        int nxt = ci + 1;
        if (nxt < nchTot)
            prefetch_chunk(sWb + bufi(nxt) * CHUNKW, gw + (size_t)nxt * 4096,
                           (nxt == nchTot - 1) ? lastRows : 32, tid, 256);
        else commit_empty();
        wait1();
        __syncthreads();
        chunk_mma8<32>(sWb + bufi(ci) * CHUNKW, sA, lda, cc * 32, acc,
                       lrow, lcol8, mr0, nc0);
        ci++;
    }
    return ci;
}

// ---------------- weight packing ----------------
__global__ void k_prep(const float* __restrict__ W_node, const float* __restrict__ fc1,
                       const float* __restrict__ fc2, const float* __restrict__ fc3,
                       const float* __restrict__ W_sh, const float* __restrict__ aW1,
                       const float* __restrict__ aW2, const float* __restrict__ aW3,
                       const float* __restrict__ W_out)
{
    int i = blockIdx.x * blockDim.x + threadIdx.x;
    int row = i >> 7, col = i & 127;
    if (i < 256 * 128) {
        float v = (row < 128) ? aW1[row * 128 + col] : W_node[(row - 128) * 128 + col];
        g_wnp[i] = __float2bfloat16(v);
    }
    if (i < 160 * 128) {
        float v = (row < 32) ? aW1[(128 + row) * 128 + col] : aW2[(row - 32) * 128 + col];
        g_watt[i] = __float2bfloat16(v);
    }
    if (i < 304 * 128) {
        float v;
        if (row < 32)       v = fc1[row * 128 + col];
        else if (row < 160) v = fc2[(row - 32) * 128 + col];
        else if (row < 288) v = fc3[(row - 160) * 128 + col];
        else                v = W_sh[(row - 288) * 128 + col];
        g_wmsg[i] = __float2bfloat16(v);
    }
    if (i < 128 * 128) g_wout[i] = __float2bfloat16(W_out[i]);
    if (i < 128 * 8) g_w3[i] = __float2bfloat16(aW3[i]);
}

__global__ void k_init()
{
    int i = blockIdx.x * blockDim.x + threadIdx.x;
    int stride = gridDim.x * blockDim.x;
    float4 z = make_float4(0.f, 0.f, 0.f, 0.f);
    for (int j = i; j < NN * DD / 4; j += stride) ((float4*)g_agg)[j] = z;
    if (i < NH) g_sum[i] = 0.f;
}

// ---------------- node projections: P1, P2, XW ----------------
__global__ void __launch_bounds__(256, 3)
k_nodeproj(const float* __restrict__ nf)
{
    extern __shared__ char smem[];
    __nv_bfloat16* s_A  = (__nv_bfloat16*)smem;             // 21504
    __nv_bfloat16* s_Wb = (__nv_bfloat16*)(smem + 21504);   // 26112

    const int tid = threadIdx.x, lane = tid & 31, wid = tid >> 5;
    const int r = lane >> 2, c = lane & 3;
    const int lrow = lane & 15, lcol8 = (lane >> 1) & 8;
    const int mr0 = (wid & 3) * 16, nc0 = (wid >> 2) * 64;
    const int n0 = blockIdx.x * 64;

    prefetch_chunk(s_Wb, g_wnp, 32, tid, 256);

#pragma unroll
    for (int i = 0; i < 8; i++) {
        int rr = wid * 8 + i;
        int n = n0 + rr; if (n >= NN) n = NN - 1;
        const float4 v = *(const float4*)(nf + (size_t)n * DD + lane * 4);
        *(__nv_bfloat162*)(s_A + rr * SA + lane * 4)     = __floats2bfloat162_rn(v.x, v.y);
        *(__nv_bfloat162*)(s_A + rr * SA + lane * 4 + 2) = __floats2bfloat162_rn(v.z, v.w);
    }

    float acc[8][4];
    clr8(acc);
    int ci = pipe8(0, 2, 8, 32, g_wnp, s_Wb, s_A, SA, acc, tid, lrow, lcol8, mr0, nc0);
#pragma unroll
    for (int nt = 0; nt < 8; nt++) {
        int col = nc0 + nt * 8 + 2 * c;
        int row0 = n0 + mr0 + r, row1 = row0 + 8;
        if (row0 < NN) *(__nv_bfloat162*)(g_P1 + (size_t)row0 * DD + col) =
            __floats2bfloat162_rn(acc[nt][0], acc[nt][1]);
        if (row1 < NN) *(__nv_bfloat162*)(g_P1 + (size_t)row1 * DD + col) =
            __floats2bfloat162_rn(acc[nt][2], acc[nt][3]);
    }
    clr8(acc);
    ci = pipe8(ci, 2, 8, 32, g_wnp, s_Wb, s_A, SA, acc, tid, lrow, lcol8, mr0, nc0);
#pragma unroll
    for (int nt = 0; nt < 8; nt++) {
        int col = nc0 + nt * 8 + 2 * c;
        int row0 = n0 + mr0 + r, row1 = row0 + 8;
        if (row0 < NN) *(__nv_bfloat162*)(g_P2 + (size_t)row0 * DD + col) =
            __floats2bfloat162_rn(acc[nt][0], acc[nt][1]);
        if (row1 < NN) *(__nv_bfloat162*)(g_P2 + (size_t)row1 * DD + col) =
            __floats2bfloat162_rn(acc[nt][2], acc[nt][3]);
    }
    clr8(acc);
    ci = pipe8(ci, 4, 8, 32, g_wnp, s_Wb, s_A, SA, acc, tid, lrow, lcol8, mr0, nc0);
#pragma unroll
    for (int nt = 0; nt < 8; nt++) {
        int col = nc0 + nt * 8 + 2 * c;
        int row0 = n0 + mr0 + r, row1 = row0 + 8;
        if (row0 < NN) *(__nv_bfloat162*)(g_XW + (size_t)row0 * DD + col) =
            __floats2bfloat162_rn(acc[nt][0], acc[nt][1]);
        if (row1 < NN) *(__nv_bfloat162*)(g_XW + (size_t)row1 * DD + col) =
            __floats2bfloat162_rn(acc[nt][2], acc[nt][3]);
    }
}

// ---------------- K1: attention -> exp(logits) bf16 + fused per-head sums ----------------
// smem: s_Wb 26112 | s_ea 5120 | s_pd 17408 | s_w3 2048 | bias 1024 | ab3 32 |
//       hsum 32 | src 256 | dst 256 => 52288
__global__ void __launch_bounds__(128, 4)
k_att(const float* __restrict__ edge_attr,
      const float* __restrict__ ab1, const float* __restrict__ ab2,
      const float* __restrict__ ab3, const int* __restrict__ edge_index)
{
    extern __shared__ char smem[];
    __nv_bfloat16* s_Wb = (__nv_bfloat16*)smem;                 // 26112
    __nv_bfloat16* s_ea = (__nv_bfloat16*)(smem + 26112);       // 5120
    __nv_bfloat16* s_pd = (__nv_bfloat16*)(smem + 31232);       // 17408
    __nv_bfloat16* s_w3 = (__nv_bfloat16*)(smem + 48640);       // 2048
    float* s_bias = (float*)(smem + 50688);                     // 1024
    float* s_ab3  = (float*)(smem + 51712);                     // 32
    float* s_hsum = (float*)(smem + 51744);                     // 32
    int*   s_src  = (int*)(smem + 51776);                       // 256
    int*   s_dst  = (int*)(smem + 52032);                       // 256

    const int tid = threadIdx.x, lane = tid & 31, wid = tid >> 5;
    const int r = lane >> 2, c = lane & 3;
    const int lrow = lane & 15, lcol8 = (lane >> 1) & 8;
    const int mr0 = wid * 16;
    const int e0 = blockIdx.x * TE;

    prefetch_chunk(s_Wb, g_watt, 32, tid, 128);

    if (tid < TE) {
        s_src[tid] = edge_index[e0 + tid];
        s_dst[tid] = edge_index[EE + e0 + tid];
    }
    s_bias[tid]       = ab1[tid];
    s_bias[128 + tid] = ab2[tid];
    if (tid < NH) { s_ab3[tid] = ab3[tid]; s_hsum[tid] = 0.f; }
    ((uint4*)s_w3)[tid] = ((const uint4*)g_w3)[tid];

    for (int idx = tid; idx < TE * 8; idx += 128) {
        int rr = idx >> 3, cc = (idx & 7) << 2;
        const float4 v = *(const float4*)(edge_attr + (size_t)(e0 + rr) * 32 + cc);
        *(__nv_bfloat162*)(s_ea + rr * SEA + cc)     = __floats2bfloat162_rn(v.x, v.y);
        *(__nv_bfloat162*)(s_ea + rr * SEA + cc + 2) = __floats2bfloat162_rn(v.z, v.w);
    }
    __syncthreads();
    // gather P1[src] + P2[dst] -> s_pd (warp-private rows)
#pragma unroll
    for (int i = 0; i < 16; i++) {
        int rr = mr0 + i;
        int s = s_src[rr], d = s_dst[rr];
        __nv_bfloat162 a0 = *(const __nv_bfloat162*)(g_P1 + (size_t)s * DD + lane * 4);
        __nv_bfloat162 a1 = *(const __nv_bfloat162*)(g_P1 + (size_t)s * DD + lane * 4 + 2);
        __nv_bfloat162 b0 = *(const __nv_bfloat162*)(g_P2 + (size_t)d * DD + lane * 4);
        __nv_bfloat162 b1 = *(const __nv_bfloat162*)(g_P2 + (size_t)d * DD + lane * 4 + 2);
        float2 f0 = __bfloat1622float2(a0), f1 = __bfloat1622float2(b0);
        float2 f2 = __bfloat1622float2(a1), f3 = __bfloat1622float2(b1);
        *(__nv_bfloat162*)(s_pd + rr * PS + lane * 4) =
            __floats2bfloat162_rn(f0.x + f1.x, f0.y + f1.y);
        *(__nv_bfloat162*)(s_pd + rr * PS + lane * 4 + 2) =
            __floats2bfloat162_rn(f2.x + f3.x, f2.y + f3.y);
    }

    float acc[16][4];
    unsigned aP[32];
    // layer1: ea @ aW1_e (chunk 0)
    clr16(acc);
    int ci = pipe_s32(0, 5, 32, g_watt, s_Wb, s_ea, SEA, acc, tid, lrow, lcol8, mr0);
#pragma unroll
    for (int nt = 0; nt < 16; nt++) {
        int col = 8 * nt + 2 * c;
        float b0 = s_bias[col], b1 = s_bias[col + 1];
        float2 p0 = __bfloat1622float2(*(const __nv_bfloat162*)(s_pd + (mr0 + r) * PS + col));
        float2 p1 = __bfloat1622float2(*(const __nv_bfloat162*)(s_pd + (mr0 + r + 8) * PS + col));
        aP[2 * nt]     = packbf(siluf(acc[nt][0] + p0.x + b0), siluf(acc[nt][1] + p0.y + b1));
        aP[2 * nt + 1] = packbf(siluf(acc[nt][2] + p1.x + b0), siluf(acc[nt][3] + p1.y + b1));
    }
    // layer2: aW2 (chunks 1-4), A from registers
    clr16(acc);
    ci = pipe_r(ci, 4, 5, 32, g_watt, s_Wb, aP, acc, tid, lrow, lcol8);
#pragma unroll
    for (int nt = 0; nt < 16; nt++) {
        int col = 8 * nt + 2 * c;
        float b0 = s_bias[128 + col], b1 = s_bias[128 + col + 1];
        aP[2 * nt]     = packbf(siluf(acc[nt][0] + b0), siluf(acc[nt][1] + b1));
        aP[2 * nt + 1] = packbf(siluf(acc[nt][2] + b0), siluf(acc[nt][3] + b1));
    }
    // logit layer: K=128 from registers, B = s_w3 (n=8)
    float la[4] = {0.f, 0.f, 0.f, 0.f};
#pragma unroll
    for (int ks = 0; ks < 8; ks++) {
        unsigned b0, b1;
        ldsm2t(b0, b1, cvta(s_w3 + (16 * ks + lrow) * 8));
        unsigned av[4] = {aP[4 * ks], aP[4 * ks + 1], aP[4 * ks + 2], aP[4 * ks + 3]};
        mma16(la, av, b0, b1);
    }
    float h0 = s_ab3[2 * c], h1 = s_ab3[2 * c + 1];
    float e00 = __expf(la[0] + h0), e01 = __expf(la[1] + h1);
    float e10 = __expf(la[2] + h0), e11 = __expf(la[3] + h1);
    *(unsigned*)(g_a + (size_t)(e0 + mr0 + r) * NH + 2 * c)     = packbf(e00, e01);
    *(unsigned*)(g_a + (size_t)(e0 + mr0 + r + 8) * NH + 2 * c) = packbf(e10, e11);

    // fused per-head sums (fp32 register values): reduce over rows, smem, global
    float s0 = e00 + e10, s1 = e01 + e11;
#pragma unroll
    for (int o = 4; o < 32; o <<= 1) {
        s0 += __shfl_xor_sync(0xffffffffu, s0, o);
        s1 += __shfl_xor_sync(0xffffffffu, s1, o);
    }
    if (lane < 4) {
        atomicAdd(&s_hsum[2 * lane], s0);
        atomicAdd(&s_hsum[2 * lane + 1], s1);
    }
    __syncthreads();
    if (tid < NH) atomicAdd(&g_sum[tid], s_hsum[tid]);
}

// ---------------- K3: message MLP + weighted scatter (R13 layout) ----------------
// smem: s_Wb 26112 | s_ea 5120 | s_x 17408 | s_sh 3072 | bias 1536 | wt 256 |
//       ish 32 | src 256 | dst 256 => 54048
__global__ void __launch_bounds__(128, 4)
k_msg(const float* __restrict__ edge_attr, const float* __restrict__ edge_sh,
      const float* __restrict__ b1, const float* __restrict__ b2,
      const float* __restrict__ b3v, const int* __restrict__ edge_index)
{
    extern __shared__ char smem[];
    __nv_bfloat16* s_Wb = (__nv_bfloat16*)smem;                 // 26112
    __nv_bfloat16* s_ea = (__nv_bfloat16*)(smem + 26112);       // 5120
    __nv_bfloat16* s_x  = (__nv_bfloat16*)(smem + 31232);       // 17408
    __nv_bfloat16* s_sh = (__nv_bfloat16*)(smem + 48640);       // 3072
    float* s_bias = (float*)(smem + 51712);                     // 1536
    float* s_wt   = (float*)(smem + 53248);                     // 256
    float* s_ish  = (float*)(smem + 53504);                     // 32
    int*   s_src  = (int*)(smem + 53536);                       // 256
    int*   s_dst  = (int*)(smem + 53792);                       // 256

    const int tid = threadIdx.x, lane = tid & 31, wid = tid >> 5;
    const int r = lane >> 2, c = lane & 3;
    const int lrow = lane & 15, lcol8 = (lane >> 1) & 8;
    const int mr0 = wid * 16;
    const int e0 = blockIdx.x * TE;

    prefetch_chunk(s_Wb, g_wmsg, 32, tid, 128);

    if (tid < TE) {
        s_src[tid] = edge_index[e0 + tid];
        s_dst[tid] = edge_index[EE + e0 + tid];
    }
    s_bias[tid]       = b1[tid];
    s_bias[128 + tid] = b2[tid];
    s_bias[256 + tid] = b3v[tid];
    if (tid < NH) s_ish[tid] = 0.125f / g_sum[tid];
    for (int idx = tid; idx < TE * 4; idx += 128) {
        int rr = idx >> 2, cc = (idx & 3) << 2;
        const float4 v = *(const float4*)(edge_sh + (size_t)(e0 + rr) * 16 + cc);
        *(__nv_bfloat162*)(s_sh + rr * SSH + cc)     = __floats2bfloat162_rn(v.x, v.y);
        *(__nv_bfloat162*)(s_sh + rr * SSH + cc + 2) = __floats2bfloat162_rn(v.z, v.w);
    }
    for (int idx = tid; idx < TE * 8; idx += 128) {
        int rr = idx >> 3, cc = (idx & 7) << 2;
        const float4 v = *(const float4*)(edge_attr + (size_t)(e0 + rr) * 32 + cc);
        *(__nv_bfloat162*)(s_ea + rr * SEA + cc)     = __floats2bfloat162_rn(v.x, v.y);
        *(__nv_bfloat162*)(s_ea + rr * SEA + cc + 2) = __floats2bfloat162_rn(v.z, v.w);
    }
    __syncthreads();
    if (tid < TE) {   // per-edge softmax-mean weight from bf16 exp values
        const uint4 ev = *(const uint4*)(g_a + (size_t)(e0 + tid) * NH);
        float2 v0 = __bfloat1622float2(*(__nv_bfloat162*)&ev.x);
        float2 v1 = __bfloat1622float2(*(__nv_bfloat162*)&ev.y);
        float2 v2 = __bfloat1622float2(*(__nv_bfloat162*)&ev.z);
        float2 v3 = __bfloat1622float2(*(__nv_bfloat162*)&ev.w);
        s_wt[tid] = v0.x * s_ish[0] + v0.y * s_ish[1] + v1.x * s_ish[2] + v1.y * s_ish[3]
                  + v2.x * s_ish[4] + v2.y * s_ish[5] + v3.x * s_ish[6] + v3.y * s_ish[7];
    }
    // gather XW[src] -> s_x (warp-private rows)
#pragma unroll
    for (int i = 0; i < 16; i++) {
        int rr = mr0 + i;
        const uint2 v = *(const uint2*)(g_XW + (size_t)s_src[rr] * DD + lane * 4);
        *(uint2*)(s_x + rr * XS + lane * 4) = v;
    }

    float acc[16][4];
    unsigned aP[32];
    // fc1 (chunk 0, K=32, A = s_ea)
    clr16(acc);
    int ci = pipe_s32(0, 10, 16, g_wmsg, s_Wb, s_ea, SEA, acc, tid, lrow, lcol8, mr0);
#pragma unroll
    for (int nt = 0; nt < 16; nt++) {
        int col = 8 * nt + 2 * c;
        float b0 = s_bias[col], b1v = s_bias[col + 1];
        aP[2 * nt]     = packbf(siluf(acc[nt][0] + b0), siluf(acc[nt][1] + b1v));
        aP[2 * nt + 1] = packbf(siluf(acc[nt][2] + b0), siluf(acc[nt][3] + b1v));
    }
    // fc2 (chunks 1-4)
    clr16(acc);
    ci = pipe_r(ci, 4, 10, 16, g_wmsg, s_Wb, aP, acc, tid, lrow, lcol8);
#pragma unroll
    for (int nt = 0; nt < 16; nt++) {
        int col = 8 * nt + 2 * c;
        float b0 = s_bias[128 + col], b1v = s_bias[128 + col + 1];
        aP[2 * nt]     = packbf(siluf(acc[nt][0] + b0), siluf(acc[nt][1] + b1v));
        aP[2 * nt + 1] = packbf(siluf(acc[nt][2] + b0), siluf(acc[nt][3] + b1v));
    }
    // fc3 (chunks 5-8) -> scale (fp32 in acc)
    clr16(acc);
    ci = pipe_r(ci, 4, 10, 16, g_wmsg, s_Wb, aP, acc, tid, lrow, lcol8);
#pragma unroll
    for (int nt = 0; nt < 16; nt++) {
        int col = 8 * nt + 2 * c;
        acc[nt][0] += s_bias[256 + col];
        acc[nt][1] += s_bias[256 + col + 1];
        acc[nt][2] += s_bias[256 + col];
        acc[nt][3] += s_bias[256 + col + 1];
    }
    // prod = xw * scale -> bf16 back into s_x (frag-owned slots)
#pragma unroll
    for (int ks = 0; ks < 8; ks++) {
        unsigned xw[4];
        ldsm4(xw, cvta(s_x + (mr0 + lrow) * XS + 16 * ks + lcol8));
        float2 f;
        f = __bfloat1622float2(*(__nv_bfloat162*)&xw[0]);
        *(unsigned*)(s_x + (mr0 + r) * XS + 16 * ks + 2 * c) =
            packbf(f.x * acc[2 * ks][0], f.y * acc[2 * ks][1]);
        f = __bfloat1622float2(*(__nv_bfloat162*)&xw[1]);
        *(unsigned*)(s_x + (mr0 + r + 8) * XS + 16 * ks + 2 * c) =
            packbf(f.x * acc[2 * ks][2], f.y * acc[2 * ks][3]);
        f = __bfloat1622float2(*(__nv_bfloat162*)&xw[2]);
        *(unsigned*)(s_x + (mr0 + r) * XS + 16 * ks + 8 + 2 * c) =
            packbf(f.x * acc[2 * ks + 1][0], f.y * acc[2 * ks + 1][1]);
        f = __bfloat1622float2(*(__nv_bfloat162*)&xw[3]);
        *(unsigned*)(s_x + (mr0 + r + 8) * XS + 16 * ks + 8 + 2 * c) =
            packbf(f.x * acc[2 * ks + 1][2], f.y * acc[2 * ks + 1][3]);
    }
    // shp = edge_sh @ W_sh (chunk 9, 16 rows, A = s_sh)
    clr16(acc);
    commit_empty();
    wait1();
    __syncthreads();
    cmma_s<16>(s_Wb + bufi(ci) * CHUNKW, s_sh, SSH, acc, lrow, lcol8, mr0);
    // msg = silu(prod + shp) * wt -> s_x
    float w0 = s_wt[mr0 + r], w1 = s_wt[mr0 + r + 8];
#pragma unroll
    for (int nt = 0; nt < 16; nt++) {
        int col = 8 * nt + 2 * c;
        float2 p0 = __bfloat1622float2(*(__nv_bfloat162*)(s_x + (mr0 + r) * XS + col));
        float2 p1 = __bfloat1622float2(*(__nv_bfloat162*)(s_x + (mr0 + r + 8) * XS + col));
        *(unsigned*)(s_x + (mr0 + r) * XS + col) =
            packbf(siluf(p0.x + acc[nt][0]) * w0, siluf(p0.y + acc[nt][1]) * w0);
        *(unsigned*)(s_x + (mr0 + r + 8) * XS + col) =
            packbf(siluf(p1.x + acc[nt][2]) * w1, siluf(p1.y + acc[nt][3]) * w1);
    }
    __syncwarp();
    // scatter: 16 warp-private rows, row-coalesced atomics
#pragma unroll
    for (int i = 0; i < 16; i++) {
        int rr = mr0 + i;
        int d = s_dst[rr];
        __nv_bfloat162 p0 = *(__nv_bfloat162*)(s_x + rr * XS + lane * 4);
        __nv_bfloat162 p1 = *(__nv_bfloat162*)(s_x + rr * XS + lane * 4 + 2);
        float2 f0 = __bfloat1622float2(p0), f1 = __bfloat1622float2(p1);
        float* p = g_agg + (size_t)d * DD + lane * 4;
        atomicAdd(p + 0, f0.x);
        atomicAdd(p + 1, f0.y);
        atomicAdd(p + 2, f1.x);
        atomicAdd(p + 3, f1.y);
    }
}

// ---------------- K4: out = LN(nf + agg @ W_out), MMA version ----------------
// smem: s_A 21504 | s_Wb 26112 | s_red 1024 => 48640
__global__ void __launch_bounds__(256, 3)
k_node(const float* __restrict__ nf, float* __restrict__ out)
{
    extern __shared__ char smem[];
    __nv_bfloat16* s_A  = (__nv_bfloat16*)smem;             // 21504
    __nv_bfloat16* s_Wb = (__nv_bfloat16*)(smem + 21504);   // 26112
    float* s_red = (float*)(smem + 47616);                  // 64 rows x 2 halves x 2

    const int tid = threadIdx.x, lane = tid & 31, wid = tid >> 5;
    const int r = lane >> 2, c = lane & 3;
    const int lrow = lane & 15, lcol8 = (lane >> 1) & 8;
    const int mr0 = (wid & 3) * 16, nc0 = (wid >> 2) * 64;
    const int half = wid >> 2;
    const int n0 = blockIdx.x * 64;

    prefetch_chunk(s_Wb, g_wout, 32, tid, 256);

#pragma unroll
    for (int i = 0; i < 8; i++) {
        int rr = wid * 8 + i;
        int n = n0 + rr; if (n >= NN) n = NN - 1;
        const float4 v = *(const float4*)(g_agg + (size_t)n * DD + lane * 4);
        *(__nv_bfloat162*)(s_A + rr * SA + lane * 4)     = __floats2bfloat162_rn(v.x, v.y);
        *(__nv_bfloat162*)(s_A + rr * SA + lane * 4 + 2) = __floats2bfloat162_rn(v.z, v.w);
    }

    float acc[8][4];
    clr8(acc);
    pipe8(0, 4, 4, 32, g_wout, s_Wb, s_A, SA, acc, tid, lrow, lcol8, mr0, nc0);

    const int lr0 = mr0 + r, lr1 = lr0 + 8;
    int row0 = n0 + lr0, row1 = n0 + lr1;
    int cr0 = row0 < NN ? row0 : NN - 1;
    int cr1 = row1 < NN ? row1 : NN - 1;
    float sum0 = 0.f, sq0 = 0.f, sum1 = 0.f, sq1 = 0.f;
#pragma unroll
    for (int nt = 0; nt < 8; nt++) {
        int col = nc0 + nt * 8 + 2 * c;
        const float2 x0 = *(const float2*)(nf + (size_t)cr0 * DD + col);
        const float2 x1 = *(const float2*)(nf + (size_t)cr1 * DD + col);
        acc[nt][0] += x0.x; acc[nt][1] += x0.y;
        acc[nt][2] += x1.x; acc[nt][3] += x1.y;
        sum0 += acc[nt][0] + acc[nt][1];
        sq0  += acc[nt][0] * acc[nt][0] + acc[nt][1] * acc[nt][1];
        sum1 += acc[nt][2] + acc[nt][3];
        sq1  += acc[nt][2] * acc[nt][2] + acc[nt][3] * acc[nt][3];
    }
    // quad reduce over c (lanes r*4+c)
#pragma unroll
    for (int o = 1; o < 4; o <<= 1) {
        sum0 += __shfl_xor_sync(0xffffffffu, sum0, o);
        sq0  += __shfl_xor_sync(0xffffffffu, sq0,  o);
        sum1 += __shfl_xor_sync(0xffffffffu, sum1, o);
        sq1  += __shfl_xor_sync(0xffffffffu, sq1,  o);
    }
    if (c == 0) {
        s_red[(lr0 * 2 + half) * 2 + 0] = sum0;
        s_red[(lr0 * 2 + half) * 2 + 1] = sq0;
        s_red[(lr1 * 2 + half) * 2 + 0] = sum1;
        s_red[(lr1 * 2 + half) * 2 + 1] = sq1;
    }
    __syncthreads();
    float ts0 = s_red[(lr0 * 2 + 0) * 2 + 0] + s_red[(lr0 * 2 + 1) * 2 + 0];
    float tq0 = s_red[(lr0 * 2 + 0) * 2 + 1] + s_red[(lr0 * 2 + 1) * 2 + 1];
    float ts1 = s_red[(lr1 * 2 + 0) * 2 + 0] + s_red[(lr1 * 2 + 1) * 2 + 0];
    float tq1 = s_red[(lr1 * 2 + 0) * 2 + 1] + s_red[(lr1 * 2 + 1) * 2 + 1];
    float mu0 = ts0 * (1.f / 128.f);
    float mu1 = ts1 * (1.f / 128.f);
    float rs0 = rsqrtf(tq0 * (1.f / 128.f) - mu0 * mu0 + 1e-5f);
    float rs1 = rsqrtf(tq1 * (1.f / 128.f) - mu1 * mu1 + 1e-5f);
#pragma unroll
    for (int nt = 0; nt < 8; nt++) {
        int col = nc0 + nt * 8 + 2 * c;
        if (row0 < NN)
            *(float2*)(out + (size_t)row0 * DD + col) =
                make_float2((acc[nt][0] - mu0) * rs0, (acc[nt][1] - mu0) * rs0);
        if (row1 < NN)
            *(float2*)(out + (size_t)row1 * DD + col) =
                make_float2((acc[nt][2] - mu1) * rs1, (acc[nt][3] - mu1) * rs1);
    }
}

extern "C" void kernel_launch(void* const* d_in, const int* in_sizes, int n_in,
                              void* d_out, int out_size)
{
    const float* nf        = (const float*)d_in[0];
    const float* edge_attr = (const float*)d_in[1];
    const float* edge_sh   = (const float*)d_in[2];
    const float* W_node    = (const float*)d_in[3];
    const float* fc1 = (const float*)d_in[4];
    const float* b1  = (const float*)d_in[5];
    const float* fc2 = (const float*)d_in[6];
    const float* b2  = (const float*)d_in[7];
    const float* fc3 = (const float*)d_in[8];
    const float* b3  = (const float*)d_in[9];
    const float* W_sh = (const float*)d_in[10];
    const float* aW1 = (const float*)d_in[11];
    const float* ab1 = (const float*)d_in[12];
    const float* aW2 = (const float*)d_in[13];
    const float* ab2 = (const float*)d_in[14];
    const float* aW3 = (const float*)d_in[15];
    const float* ab3 = (const float*)d_in[16];
    const float* W_out = (const float*)d_in[17];
    const int* edge_index = (const int*)d_in[18];
    float* out = (float*)d_out;

    const int SMEM_NP   = 47616;
    const int SMEM_ATT  = 52288;
    const int SMEM_MSG  = 54048;
    const int SMEM_NODE = 48640;
    cudaFuncSetAttribute(k_nodeproj, cudaFuncAttributeMaxDynamicSharedMemorySize, SMEM_NP);
    cudaFuncSetAttribute(k_att,  cudaFuncAttributeMaxDynamicSharedMemorySize, SMEM_ATT);
    cudaFuncSetAttribute(k_msg,  cudaFuncAttributeMaxDynamicSharedMemorySize, SMEM_MSG);
    cudaFuncSetAttribute(k_node, cudaFuncAttributeMaxDynamicSharedMemorySize, SMEM_NODE);

    k_prep<<<152, 256>>>(W_node, fc1, fc2, fc3, W_sh, aW1, aW2, aW3, W_out);
    k_init<<<2048, 256>>>();
    k_nodeproj<<<(NN + 63) / 64, 256, SMEM_NP>>>(nf);
    k_att<<<EE / TE, 128, SMEM_ATT>>>(edge_attr, ab1, ab2, ab3, edge_index);
    k_msg<<<EE / TE, 128, SMEM_MSG>>>(edge_attr, edge_sh, b1, b2, b3, edge_index);
    k_node<<<(NN + 63) / 64, 256, SMEM_NODE>>>(nf, out);
}

// round 16
// speedup vs baseline: 1.2885x; 1.0111x over previous
#include <cuda_runtime.h>
#include <cuda_bf16.h>

#define NN 50000
#define EE 800000
#define DD 128
#define NH 8
#define TE 64
#define SA 168
#define WS2 136
#define SSH 24
#define SEA 40
#define XS 136
#define PS 136
#define CHUNKW (32 * WS2)

__device__ __nv_bfloat16 g_a[(size_t)EE * NH];   // exp(logit) per edge/head (bf16)
__device__ float    g_agg[(size_t)NN * DD];
__device__ float    g_sum[NH];
__device__ __align__(256) __nv_bfloat16 g_wnp[256 * 128];   // aW1[0:128) | W_node
__device__ __align__(256) __nv_bfloat16 g_watt[160 * 128];  // aW1[128:160) | aW2
__device__ __align__(256) __nv_bfloat16 g_wmsg[304 * 128];  // fc1|fc2|fc3|W_sh
__device__ __align__(256) __nv_bfloat16 g_w3[128 * 8];      // aW3 bf16
__device__ __align__(256) __nv_bfloat16 g_wout[128 * 128];  // W_out bf16
__device__ __align__(256) __nv_bfloat16 g_P1[(size_t)NN * DD];
__device__ __align__(256) __nv_bfloat16 g_P2[(size_t)NN * DD];
__device__ __align__(256) __nv_bfloat16 g_XW[(size_t)NN * DD];

__device__ __forceinline__ float siluf(float x) {
    float t;
    asm("tanh.approx.f32 %0, %1;" : "=f"(t) : "f"(x * 0.5f));
    return 0.5f * x * (1.f + t);
}
__device__ __forceinline__ void ldsm4(unsigned (&r)[4], unsigned addr) {
    asm volatile("ldmatrix.sync.aligned.m8n8.x4.shared.b16 {%0,%1,%2,%3}, [%4];"
                 : "=r"(r[0]), "=r"(r[1]), "=r"(r[2]), "=r"(r[3]) : "r"(addr));
}
__device__ __forceinline__ void ldsm4t(unsigned* r, unsigned addr) {
    asm volatile("ldmatrix.sync.aligned.m8n8.x4.trans.shared.b16 {%0,%1,%2,%3}, [%4];"
                 : "=r"(r[0]), "=r"(r[1]), "=r"(r[2]), "=r"(r[3]) : "r"(addr));
}
__device__ __forceinline__ void ldsm2t(unsigned& r0, unsigned& r1, unsigned addr) {
    asm volatile("ldmatrix.sync.aligned.m8n8.x2.trans.shared.b16 {%0,%1}, [%2];"
                 : "=r"(r0), "=r"(r1) : "r"(addr));
}
__device__ __forceinline__ void mma16(float (&d)[4], const unsigned (&a)[4],
                                      unsigned b0, unsigned b1) {
    asm volatile(
        "mma.sync.aligned.m16n8k16.row.col.f32.bf16.bf16.f32 "
        "{%0,%1,%2,%3}, {%4,%5,%6,%7}, {%8,%9}, {%0,%1,%2,%3};\n"
        : "+f"(d[0]), "+f"(d[1]), "+f"(d[2]), "+f"(d[3])
        : "r"(a[0]), "r"(a[1]), "r"(a[2]), "r"(a[3]), "r"(b0), "r"(b1));
}
__device__ __forceinline__ unsigned cvta(const void* p) {
    return (unsigned)__cvta_generic_to_shared(p);
}
__device__ __forceinline__ unsigned packbf(float a, float b) {
    __nv_bfloat162 v = __floats2bfloat162_rn(a, b);
    return *(unsigned*)&v;
}
__device__ __forceinline__ void clr16(float (&acc)[16][4]) {
#pragma unroll
    for (int i = 0; i < 16; i++)
#pragma unroll
        for (int j = 0; j < 4; j++) acc[i][j] = 0.f;
}
__device__ __forceinline__ void clr8(float (&acc)[8][4]) {
#pragma unroll
    for (int i = 0; i < 8; i++)
#pragma unroll
        for (int j = 0; j < 4; j++) acc[i][j] = 0.f;
}

__device__ __forceinline__ void prefetch_chunk(__nv_bfloat16* sbuf,
        const __nv_bfloat16* __restrict__ gsrc, int nrows, int tid, int nthr)
{
    for (int idx = tid; idx < nrows * 16; idx += nthr) {
        int row = idx >> 4, seg = idx & 15;
        unsigned d = cvta(sbuf + row * WS2) + seg * 16;
        const char* s = (const char*)(gsrc + (size_t)row * 128) + seg * 16;
        asm volatile("cp.async.cg.shared.global [%0], [%1], 16;" :: "r"(d), "l"(s));
    }
    asm volatile("cp.async.commit_group;" ::: "memory");
}
__device__ __forceinline__ void commit_empty() {
    asm volatile("cp.async.commit_group;" ::: "memory");
}
__device__ __forceinline__ void wait1() {
    asm volatile("cp.async.wait_group 1;" ::: "memory");
}
__device__ __forceinline__ int bufi(int ci) { return ci % 3; }

// ===== 4-warp chain tile: warp = 16 rows x 128 cols, acc[16][4] =====
template<int NK>
__device__ __forceinline__ void cmma_s(const __nv_bfloat16* sW,
        const __nv_bfloat16* sA, int lda, float (&acc)[16][4],
        int lrow, int lcol8, int mr0)
{
#pragma unroll
    for (int ks = 0; ks < NK / 16; ks++) {
        unsigned a[4];
        ldsm4(a, cvta(sA + (mr0 + lrow) * lda + ks * 16 + lcol8));
#pragma unroll
        for (int np = 0; np < 8; np++) {
            unsigned bb[4];
            ldsm4t(bb, cvta(sW + (ks * 16 + lrow) * WS2 + np * 16 + lcol8));
            mma16(acc[2 * np], a, bb[0], bb[1]);
            mma16(acc[2 * np + 1], a, bb[2], bb[3]);
        }
    }
}
__device__ __forceinline__ void cmma_r(const __nv_bfloat16* sW,
        const unsigned* aP, int cc, float (&acc)[16][4], int lrow, int lcol8)
{
#pragma unroll
    for (int ks = 0; ks < 2; ks++) {
        const int kg = 2 * cc + ks;
        unsigned a[4] = {aP[4 * kg], aP[4 * kg + 1], aP[4 * kg + 2], aP[4 * kg + 3]};
#pragma unroll
        for (int np = 0; np < 8; np++) {
            unsigned bb[4];
            ldsm4t(bb, cvta(sW + (ks * 16 + lrow) * WS2 + np * 16 + lcol8));
            mma16(acc[2 * np], a, bb[0], bb[1]);
            mma16(acc[2 * np + 1], a, bb[2], bb[3]);
        }
    }
}
// one K=32 chunk, A from shared; triple-buffered, ONE sync per chunk
__device__ __forceinline__ int pipe_s32(int ci, int nchTot, int lastRows,
        const __nv_bfloat16* __restrict__ gw, __nv_bfloat16* sWb,
        const __nv_bfloat16* sA, int lda, float (&acc)[16][4],
        int tid, int lrow, int lcol8, int mr0)
{
    int nxt = ci + 1;
    if (nxt < nchTot)
        prefetch_chunk(sWb + bufi(nxt) * CHUNKW, gw + (size_t)nxt * 4096,
                       (nxt == nchTot - 1) ? lastRows : 32, tid, 128);
    else commit_empty();
    wait1();
    __syncthreads();
    cmma_s<32>(sWb + bufi(ci) * CHUNKW, sA, lda, acc, lrow, lcol8, mr0);
    return ci + 1;
}
// nc K=32 chunks, A from registers
__device__ __forceinline__ int pipe_r(int ci, int nc, int nchTot, int lastRows,
        const __nv_bfloat16* __restrict__ gw, __nv_bfloat16* sWb,
        const unsigned* aP, float (&acc)[16][4],
        int tid, int lrow, int lcol8)
{
    for (int cc = 0; cc < nc; cc++) {
        int nxt = ci + 1;
        if (nxt < nchTot)
            prefetch_chunk(sWb + bufi(nxt) * CHUNKW, gw + (size_t)nxt * 4096,
                           (nxt == nchTot - 1) ? lastRows : 32, tid, 128);
        else commit_empty();
        wait1();
        __syncthreads();
        cmma_r(sWb + bufi(ci) * CHUNKW, aP, cc, acc, lrow, lcol8);
        ci++;
    }
    return ci;
}

// ===== 8-warp helpers (nodeproj + k_node; 256 threads, acc[8][4]) =====
template<int NK>
__device__ __forceinline__ void chunk_mma8(const __nv_bfloat16* sW,
        const __nv_bfloat16* sA, int lda, int kc, float (&acc)[8][4],
        int lrow, int lcol8, int mr0, int nc0)
{
#pragma unroll
    for (int k0 = 0; k0 < NK; k0 += 16) {
        unsigned a[4];
        ldsm4(a, cvta(sA + (mr0 + lrow) * lda + kc + k0 + lcol8));
        unsigned b[16];
#pragma unroll
        for (int np = 0; np < 4; np++)
            ldsm4t(b + np * 4, cvta(sW + (k0 + lrow) * WS2 + nc0 + np * 16 + lcol8));
#pragma unroll
        for (int nt = 0; nt < 8; nt++)
            mma16(acc[nt], a, b[(nt >> 1) * 4 + (nt & 1) * 2],
                              b[(nt >> 1) * 4 + (nt & 1) * 2 + 1]);
    }
}
__device__ __forceinline__ int pipe8(int ci, int nc, int nchTot, int lastRows,
        const __nv_bfloat16* __restrict__ gw, __nv_bfloat16* sWb,
        const __nv_bfloat16* sA, int lda, float (&acc)[8][4],
        int tid, int lrow, int lcol8, int mr0, int nc0)
{
    for (int cc = 0; cc < nc; cc++) {
        int nxt = ci + 1;
        if (nxt < nchTot)
            prefetch_chunk(sWb + bufi(nxt) * CHUNKW, gw + (size_t)nxt * 4096,
                           (nxt == nchTot - 1) ? lastRows : 32, tid, 256);
        else commit_empty();
        wait1();
        __syncthreads();
        chunk_mma8<32>(sWb + bufi(ci) * CHUNKW, sA, lda, cc * 32, acc,
                       lrow, lcol8, mr0, nc0);
        ci++;
    }
    return ci;
}

// ---------------- weight packing ----------------
__global__ void k_prep(const float* __restrict__ W_node, const float* __restrict__ fc1,
                       const float* __restrict__ fc2, const float* __restrict__ fc3,
                       const float* __restrict__ W_sh, const float* __restrict__ aW1,
                       const float* __restrict__ aW2, const float* __restrict__ aW3,
                       const float* __restrict__ W_out)
{
    int i = blockIdx.x * blockDim.x + threadIdx.x;
    int row = i >> 7, col = i & 127;
    if (i < 256 * 128) {
        float v = (row < 128) ? aW1[row * 128 + col] : W_node[(row - 128) * 128 + col];
        g_wnp[i] = __float2bfloat16(v);
    }
    if (i < 160 * 128) {
        float v = (row < 32) ? aW1[(128 + row) * 128 + col] : aW2[(row - 32) * 128 + col];
        g_watt[i] = __float2bfloat16(v);
    }
    if (i < 304 * 128) {
        float v;
        if (row < 32)       v = fc1[row * 128 + col];
        else if (row < 160) v = fc2[(row - 32) * 128 + col];
        else if (row < 288) v = fc3[(row - 160) * 128 + col];
        else                v = W_sh[(row - 288) * 128 + col];
        g_wmsg[i] = __float2bfloat16(v);
    }
    if (i < 128 * 128) g_wout[i] = __float2bfloat16(W_out[i]);
    if (i < 128 * 8) g_w3[i] = __float2bfloat16(aW3[i]);
}

__global__ void k_init()
{
    int i = blockIdx.x * blockDim.x + threadIdx.x;
    int stride = gridDim.x * blockDim.x;
    float4 z = make_float4(0.f, 0.f, 0.f, 0.f);
    for (int j = i; j < NN * DD / 4; j += stride) ((float4*)g_agg)[j] = z;
    if (i < NH) g_sum[i] = 0.f;
}

// ---------------- node projections: P1, P2, XW ----------------
__global__ void __launch_bounds__(256, 3)
k_nodeproj(const float* __restrict__ nf)
{
    extern __shared__ char smem[];
    __nv_bfloat16* s_A  = (__nv_bfloat16*)smem;             // 21504
    __nv_bfloat16* s_Wb = (__nv_bfloat16*)(smem + 21504);   // 26112

    const int tid = threadIdx.x, lane = tid & 31, wid = tid >> 5;
    const int r = lane >> 2, c = lane & 3;
    const int lrow = lane & 15, lcol8 = (lane >> 1) & 8;
    const int mr0 = (wid & 3) * 16, nc0 = (wid >> 2) * 64;
    const int n0 = blockIdx.x * 64;

    prefetch_chunk(s_Wb, g_wnp, 32, tid, 256);

#pragma unroll
    for (int i = 0; i < 8; i++) {
        int rr = wid * 8 + i;
        int n = n0 + rr; if (n >= NN) n = NN - 1;
        const float4 v = *(const float4*)(nf + (size_t)n * DD + lane * 4);
        *(__nv_bfloat162*)(s_A + rr * SA + lane * 4)     = __floats2bfloat162_rn(v.x, v.y);
        *(__nv_bfloat162*)(s_A + rr * SA + lane * 4 + 2) = __floats2bfloat162_rn(v.z, v.w);
    }

    float acc[8][4];
    clr8(acc);
    int ci = pipe8(0, 2, 8, 32, g_wnp, s_Wb, s_A, SA, acc, tid, lrow, lcol8, mr0, nc0);
#pragma unroll
    for (int nt = 0; nt < 8; nt++) {
        int col = nc0 + nt * 8 + 2 * c;
        int row0 = n0 + mr0 + r, row1 = row0 + 8;
        if (row0 < NN) *(__nv_bfloat162*)(g_P1 + (size_t)row0 * DD + col) =
            __floats2bfloat162_rn(acc[nt][0], acc[nt][1]);
        if (row1 < NN) *(__nv_bfloat162*)(g_P1 + (size_t)row1 * DD + col) =
            __floats2bfloat162_rn(acc[nt][2], acc[nt][3]);
    }
    clr8(acc);
    ci = pipe8(ci, 2, 8, 32, g_wnp, s_Wb, s_A, SA, acc, tid, lrow, lcol8, mr0, nc0);
#pragma unroll
    for (int nt = 0; nt < 8; nt++) {
        int col = nc0 + nt * 8 + 2 * c;
        int row0 = n0 + mr0 + r, row1 = row0 + 8;
        if (row0 < NN) *(__nv_bfloat162*)(g_P2 + (size_t)row0 * DD + col) =
            __floats2bfloat162_rn(acc[nt][0], acc[nt][1]);
        if (row1 < NN) *(__nv_bfloat162*)(g_P2 + (size_t)row1 * DD + col) =
            __floats2bfloat162_rn(acc[nt][2], acc[nt][3]);
    }
    clr8(acc);
    ci = pipe8(ci, 4, 8, 32, g_wnp, s_Wb, s_A, SA, acc, tid, lrow, lcol8, mr0, nc0);
#pragma unroll
    for (int nt = 0; nt < 8; nt++) {
        int col = nc0 + nt * 8 + 2 * c;
        int row0 = n0 + mr0 + r, row1 = row0 + 8;
        if (row0 < NN) *(__nv_bfloat162*)(g_XW + (size_t)row0 * DD + col) =
            __floats2bfloat162_rn(acc[nt][0], acc[nt][1]);
        if (row1 < NN) *(__nv_bfloat162*)(g_XW + (size_t)row1 * DD + col) =
            __floats2bfloat162_rn(acc[nt][2], acc[nt][3]);
    }
}

// ---------------- K1: attention -> exp(logits) bf16 + fused per-head sums ----------------
// smem: s_Wb 26112 | s_ea 5120 | s_pd 17408 | s_w3 2048 | bias 1024 | ab3 32 |
//       hsum 32 | src 256 | dst 256 => 52288
__global__ void __launch_bounds__(128, 4)
k_att(const float* __restrict__ edge_attr,
      const float* __restrict__ ab1, const float* __restrict__ ab2,
      const float* __restrict__ ab3, const int* __restrict__ edge_index)
{
    extern __shared__ char smem[];
    __nv_bfloat16* s_Wb = (__nv_bfloat16*)smem;                 // 26112
    __nv_bfloat16* s_ea = (__nv_bfloat16*)(smem + 26112);       // 5120
    __nv_bfloat16* s_pd = (__nv_bfloat16*)(smem + 31232);       // 17408
    __nv_bfloat16* s_w3 = (__nv_bfloat16*)(smem + 48640);       // 2048
    float* s_bias = (float*)(smem + 50688);                     // 1024
    float* s_ab3  = (float*)(smem + 51712);                     // 32
    float* s_hsum = (float*)(smem + 51744);                     // 32
    int*   s_src  = (int*)(smem + 51776);                       // 256
    int*   s_dst  = (int*)(smem + 52032);                       // 256

    const int tid = threadIdx.x, lane = tid & 31, wid = tid >> 5;
    const int r = lane >> 2, c = lane & 3;
    const int lrow = lane & 15, lcol8 = (lane >> 1) & 8;
    const int mr0 = wid * 16;
    const int e0 = blockIdx.x * TE;

    prefetch_chunk(s_Wb, g_watt, 32, tid, 128);

    if (tid < TE) {
        s_src[tid] = edge_index[e0 + tid];
        s_dst[tid] = edge_index[EE + e0 + tid];
    }
    s_bias[tid]       = ab1[tid];
    s_bias[128 + tid] = ab2[tid];
    if (tid < NH) { s_ab3[tid] = ab3[tid]; s_hsum[tid] = 0.f; }
    ((uint4*)s_w3)[tid] = ((const uint4*)g_w3)[tid];

    for (int idx = tid; idx < TE * 8; idx += 128) {
        int rr = idx >> 3, cc = (idx & 7) << 2;
        const float4 v = *(const float4*)(edge_attr + (size_t)(e0 + rr) * 32 + cc);
        *(__nv_bfloat162*)(s_ea + rr * SEA + cc)     = __floats2bfloat162_rn(v.x, v.y);
        *(__nv_bfloat162*)(s_ea + rr * SEA + cc + 2) = __floats2bfloat162_rn(v.z, v.w);
    }
    __syncthreads();
    // gather P1[src] + P2[dst] -> s_pd (warp-private rows)
#pragma unroll
    for (int i = 0; i < 16; i++) {
        int rr = mr0 + i;
        int s = s_src[rr], d = s_dst[rr];
        __nv_bfloat162 a0 = *(const __nv_bfloat162*)(g_P1 + (size_t)s * DD + lane * 4);
        __nv_bfloat162 a1 = *(const __nv_bfloat162*)(g_P1 + (size_t)s * DD + lane * 4 + 2);
        __nv_bfloat162 b0 = *(const __nv_bfloat162*)(g_P2 + (size_t)d * DD + lane * 4);
        __nv_bfloat162 b1 = *(const __nv_bfloat162*)(g_P2 + (size_t)d * DD + lane * 4 + 2);
        float2 f0 = __bfloat1622float2(a0), f1 = __bfloat1622float2(b0);
        float2 f2 = __bfloat1622float2(a1), f3 = __bfloat1622float2(b1);
        *(__nv_bfloat162*)(s_pd + rr * PS + lane * 4) =
            __floats2bfloat162_rn(f0.x + f1.x, f0.y + f1.y);
        *(__nv_bfloat162*)(s_pd + rr * PS + lane * 4 + 2) =
            __floats2bfloat162_rn(f2.x + f3.x, f2.y + f3.y);
    }

    float acc[16][4];
    unsigned aP[32];
    // layer1: ea @ aW1_e (chunk 0)
    clr16(acc);
    int ci = pipe_s32(0, 5, 32, g_watt, s_Wb, s_ea, SEA, acc, tid, lrow, lcol8, mr0);
#pragma unroll
    for (int nt = 0; nt < 16; nt++) {
        int col = 8 * nt + 2 * c;
        float b0 = s_bias[col], b1 = s_bias[col + 1];
        float2 p0 = __bfloat1622float2(*(const __nv_bfloat162*)(s_pd + (mr0 + r) * PS + col));
        float2 p1 = __bfloat1622float2(*(const __nv_bfloat162*)(s_pd + (mr0 + r + 8) * PS + col));
        aP[2 * nt]     = packbf(siluf(acc[nt][0] + p0.x + b0), siluf(acc[nt][1] + p0.y + b1));
        aP[2 * nt + 1] = packbf(siluf(acc[nt][2] + p1.x + b0), siluf(acc[nt][3] + p1.y + b1));
    }
    // layer2: aW2 (chunks 1-4), A from registers
    clr16(acc);
    ci = pipe_r(ci, 4, 5, 32, g_watt, s_Wb, aP, acc, tid, lrow, lcol8);
#pragma unroll
    for (int nt = 0; nt < 16; nt++) {
        int col = 8 * nt + 2 * c;
        float b0 = s_bias[128 + col], b1 = s_bias[128 + col + 1];
        aP[2 * nt]     = packbf(siluf(acc[nt][0] + b0), siluf(acc[nt][1] + b1));
        aP[2 * nt + 1] = packbf(siluf(acc[nt][2] + b0), siluf(acc[nt][3] + b1));
    }
    // logit layer: K=128 from registers, B = s_w3 (n=8)
    float la[4] = {0.f, 0.f, 0.f, 0.f};
#pragma unroll
    for (int ks = 0; ks < 8; ks++) {
        unsigned b0, b1;
        ldsm2t(b0, b1, cvta(s_w3 + (16 * ks + lrow) * 8));
        unsigned av[4] = {aP[4 * ks], aP[4 * ks + 1], aP[4 * ks + 2], aP[4 * ks + 3]};
        mma16(la, av, b0, b1);
    }
    float h0 = s_ab3[2 * c], h1 = s_ab3[2 * c + 1];
    float e00 = __expf(la[0] + h0), e01 = __expf(la[1] + h1);
    float e10 = __expf(la[2] + h0), e11 = __expf(la[3] + h1);
    *(unsigned*)(g_a + (size_t)(e0 + mr0 + r) * NH + 2 * c)     = packbf(e00, e01);
    *(unsigned*)(g_a + (size_t)(e0 + mr0 + r + 8) * NH + 2 * c) = packbf(e10, e11);

    // fused per-head sums (fp32 register values): reduce over rows, smem, global
    float s0 = e00 + e10, s1 = e01 + e11;
#pragma unroll
    for (int o = 4; o < 32; o <<= 1) {
        s0 += __shfl_xor_sync(0xffffffffu, s0, o);
        s1 += __shfl_xor_sync(0xffffffffu, s1, o);
    }
    if (lane < 4) {
        atomicAdd(&s_hsum[2 * lane], s0);
        atomicAdd(&s_hsum[2 * lane + 1], s1);
    }
    __syncthreads();
    if (tid < NH) atomicAdd(&g_sum[tid], s_hsum[tid]);
}

// ---------------- K3: message MLP + weighted scatter (reg-fused prod+shp) ----------------
// smem: s_Wb 26112 | s_ea 5120 | s_x 17408 | s_sh 3072 | bias 1536 | wt 256 |
//       ish 32 | src 256 | dst 256 => 54048
__global__ void __launch_bounds__(128, 4)
k_msg(const float* __restrict__ edge_attr, const float* __restrict__ edge_sh,
      const float* __restrict__ b1, const float* __restrict__ b2,
      const float* __restrict__ b3v, const int* __restrict__ edge_index)
{
    extern __shared__ char smem[];
    __nv_bfloat16* s_Wb = (__nv_bfloat16*)smem;                 // 26112
    __nv_bfloat16* s_ea = (__nv_bfloat16*)(smem + 26112);       // 5120
    __nv_bfloat16* s_x  = (__nv_bfloat16*)(smem + 31232);       // 17408
    __nv_bfloat16* s_sh = (__nv_bfloat16*)(smem + 48640);       // 3072
    float* s_bias = (float*)(smem + 51712);                     // 1536
    float* s_wt   = (float*)(smem + 53248);                     // 256
    float* s_ish  = (float*)(smem + 53504);                     // 32
    int*   s_src  = (int*)(smem + 53536);                       // 256
    int*   s_dst  = (int*)(smem + 53792);                       // 256

    const int tid = threadIdx.x, lane = tid & 31, wid = tid >> 5;
    const int r = lane >> 2, c = lane & 3;
    const int lrow = lane & 15, lcol8 = (lane >> 1) & 8;
    const int mr0 = wid * 16;
    const int e0 = blockIdx.x * TE;

    prefetch_chunk(s_Wb, g_wmsg, 32, tid, 128);

    if (tid < TE) {
        s_src[tid] = edge_index[e0 + tid];
        s_dst[tid] = edge_index[EE + e0 + tid];
    }
    s_bias[tid]       = b1[tid];
    s_bias[128 + tid] = b2[tid];
    s_bias[256 + tid] = b3v[tid];
    if (tid < NH) s_ish[tid] = 0.125f / g_sum[tid];
    for (int idx = tid; idx < TE * 4; idx += 128) {
        int rr = idx >> 2, cc = (idx & 3) << 2;
        const float4 v = *(const float4*)(edge_sh + (size_t)(e0 + rr) * 16 + cc);
        *(__nv_bfloat162*)(s_sh + rr * SSH + cc)     = __floats2bfloat162_rn(v.x, v.y);
        *(__nv_bfloat162*)(s_sh + rr * SSH + cc + 2) = __floats2bfloat162_rn(v.z, v.w);
    }
    for (int idx = tid; idx < TE * 8; idx += 128) {
        int rr = idx >> 3, cc = (idx & 7) << 2;
        const float4 v = *(const float4*)(edge_attr + (size_t)(e0 + rr) * 32 + cc);
        *(__nv_bfloat162*)(s_ea + rr * SEA + cc)     = __floats2bfloat162_rn(v.x, v.y);
        *(__nv_bfloat162*)(s_ea + rr * SEA + cc + 2) = __floats2bfloat162_rn(v.z, v.w);
    }
    __syncthreads();
    if (tid < TE) {   // per-edge softmax-mean weight from bf16 exp values
        const uint4 ev = *(const uint4*)(g_a + (size_t)(e0 + tid) * NH);
        float2 v0 = __bfloat1622float2(*(__nv_bfloat162*)&ev.x);
        float2 v1 = __bfloat1622float2(*(__nv_bfloat162*)&ev.y);
        float2 v2 = __bfloat1622float2(*(__nv_bfloat162*)&ev.z);
        float2 v3 = __bfloat1622float2(*(__nv_bfloat162*)&ev.w);
        s_wt[tid] = v0.x * s_ish[0] + v0.y * s_ish[1] + v1.x * s_ish[2] + v1.y * s_ish[3]
                  + v2.x * s_ish[4] + v2.y * s_ish[5] + v3.x * s_ish[6] + v3.y * s_ish[7];
    }
    // gather XW[src] -> s_x (warp-private rows)
#pragma unroll
    for (int i = 0; i < 16; i++) {
        int rr = mr0 + i;
        const uint2 v = *(const uint2*)(g_XW + (size_t)s_src[rr] * DD + lane * 4);
        *(uint2*)(s_x + rr * XS + lane * 4) = v;
    }

    float acc[16][4];
    unsigned aP[32];
    // fc1 (chunk 0, K=32, A = s_ea)
    clr16(acc);
    int ci = pipe_s32(0, 10, 16, g_wmsg, s_Wb, s_ea, SEA, acc, tid, lrow, lcol8, mr0);
#pragma unroll
    for (int nt = 0; nt < 16; nt++) {
        int col = 8 * nt + 2 * c;
        float b0 = s_bias[col], b1v = s_bias[col + 1];
        aP[2 * nt]     = packbf(siluf(acc[nt][0] + b0), siluf(acc[nt][1] + b1v));
        aP[2 * nt + 1] = packbf(siluf(acc[nt][2] + b0), siluf(acc[nt][3] + b1v));
    }
    // fc2 (chunks 1-4)
    clr16(acc);
    ci = pipe_r(ci, 4, 10, 16, g_wmsg, s_Wb, aP, acc, tid, lrow, lcol8);
#pragma unroll
    for (int nt = 0; nt < 16; nt++) {
        int col = 8 * nt + 2 * c;
        float b0 = s_bias[128 + col], b1v = s_bias[128 + col + 1];
        aP[2 * nt]     = packbf(siluf(acc[nt][0] + b0), siluf(acc[nt][1] + b1v));
        aP[2 * nt + 1] = packbf(siluf(acc[nt][2] + b0), siluf(acc[nt][3] + b1v));
    }
    // fc3 (chunks 5-8) -> scale = fc3 + b3 (fp32 in acc)
    clr16(acc);
    ci = pipe_r(ci, 4, 10, 16, g_wmsg, s_Wb, aP, acc, tid, lrow, lcol8);
#pragma unroll
    for (int nt = 0; nt < 16; nt++) {
        int col = 8 * nt + 2 * c;
        acc[nt][0] += s_bias[256 + col];
        acc[nt][1] += s_bias[256 + col + 1];
        acc[nt][2] += s_bias[256 + col];
        acc[nt][3] += s_bias[256 + col + 1];
    }
    // acc = xw * scale IN REGISTERS (A-frag layout == C-frag layout per 16-col block)
#pragma unroll
    for (int ks = 0; ks < 8; ks++) {
        unsigned xw[4];
        ldsm4(xw, cvta(s_x + (mr0 + lrow) * XS + 16 * ks + lcol8));
        float2 f;
        f = __bfloat1622float2(*(__nv_bfloat162*)&xw[0]);
        acc[2 * ks][0] *= f.x;  acc[2 * ks][1] *= f.y;
        f = __bfloat1622float2(*(__nv_bfloat162*)&xw[1]);
        acc[2 * ks][2] *= f.x;  acc[2 * ks][3] *= f.y;
        f = __bfloat1622float2(*(__nv_bfloat162*)&xw[2]);
        acc[2 * ks + 1][0] *= f.x;  acc[2 * ks + 1][1] *= f.y;
        f = __bfloat1622float2(*(__nv_bfloat162*)&xw[3]);
        acc[2 * ks + 1][2] *= f.x;  acc[2 * ks + 1][3] *= f.y;
    }
    // shp = edge_sh @ W_sh ACCUMULATED onto xw*scale (chunk 9, 16 rows, A = s_sh)
    commit_empty();
    wait1();
    __syncthreads();
    cmma_s<16>(s_Wb + bufi(ci) * CHUNKW, s_sh, SSH, acc, lrow, lcol8, mr0);
    // msg = silu(acc) * wt -> s_x (single bounce for scatter-coalescing transpose)
    float w0 = s_wt[mr0 + r], w1 = s_wt[mr0 + r + 8];
#pragma unroll
    for (int nt = 0; nt < 16; nt++) {
        int col = 8 * nt + 2 * c;
        *(unsigned*)(s_x + (mr0 + r) * XS + col) =
            packbf(siluf(acc[nt][0]) * w0, siluf(acc[nt][1]) * w0);
        *(unsigned*)(s_x + (mr0 + r + 8) * XS + col) =
            packbf(siluf(acc[nt][2]) * w1, siluf(acc[nt][3]) * w1);
    }
    __syncwarp();
    // scatter: 16 warp-private rows, row-coalesced atomics
#pragma unroll
    for (int i = 0; i < 16; i++) {
        int rr = mr0 + i;
        int d = s_dst[rr];
        __nv_bfloat162 p0 = *(__nv_bfloat162*)(s_x + rr * XS + lane * 4);
        __nv_bfloat162 p1 = *(__nv_bfloat162*)(s_x + rr * XS + lane * 4 + 2);
        float2 f0 = __bfloat1622float2(p0), f1 = __bfloat1622float2(p1);
        float* p = g_agg + (size_t)d * DD + lane * 4;
        atomicAdd(p + 0, f0.x);
        atomicAdd(p + 1, f0.y);
        atomicAdd(p + 2, f1.x);
        atomicAdd(p + 3, f1.y);
    }
}

// ---------------- K4: out = LN(nf + agg @ W_out), MMA version ----------------
// smem: s_A 21504 | s_Wb 26112 | s_red 1024 => 48640
__global__ void __launch_bounds__(256, 3)
k_node(const float* __restrict__ nf, float* __restrict__ out)
{
    extern __shared__ char smem[];
    __nv_bfloat16* s_A  = (__nv_bfloat16*)smem;             // 21504
    __nv_bfloat16* s_Wb = (__nv_bfloat16*)(smem + 21504);   // 26112
    float* s_red = (float*)(smem + 47616);                  // 64 rows x 2 halves x 2

    const int tid = threadIdx.x, lane = tid & 31, wid = tid >> 5;
    const int r = lane >> 2, c = lane & 3;
    const int lrow = lane & 15, lcol8 = (lane >> 1) & 8;
    const int mr0 = (wid & 3) * 16, nc0 = (wid >> 2) * 64;
    const int half = wid >> 2;
    const int n0 = blockIdx.x * 64;

    prefetch_chunk(s_Wb, g_wout, 32, tid, 256);

#pragma unroll
    for (int i = 0; i < 8; i++) {
        int rr = wid * 8 + i;
        int n = n0 + rr; if (n >= NN) n = NN - 1;
        const float4 v = *(const float4*)(g_agg + (size_t)n * DD + lane * 4);
        *(__nv_bfloat162*)(s_A + rr * SA + lane * 4)     = __floats2bfloat162_rn(v.x, v.y);
        *(__nv_bfloat162*)(s_A + rr * SA + lane * 4 + 2) = __floats2bfloat162_rn(v.z, v.w);
    }

    float acc[8][4];
    clr8(acc);
    pipe8(0, 4, 4, 32, g_wout, s_Wb, s_A, SA, acc, tid, lrow, lcol8, mr0, nc0);

    const int lr0 = mr0 + r, lr1 = lr0 + 8;
    int row0 = n0 + lr0, row1 = n0 + lr1;
    int cr0 = row0 < NN ? row0 : NN - 1;
    int cr1 = row1 < NN ? row1 : NN - 1;
    float sum0 = 0.f, sq0 = 0.f, sum1 = 0.f, sq1 = 0.f;
#pragma unroll
    for (int nt = 0; nt < 8; nt++) {
        int col = nc0 + nt * 8 + 2 * c;
        const float2 x0 = *(const float2*)(nf + (size_t)cr0 * DD + col);
        const float2 x1 = *(const float2*)(nf + (size_t)cr1 * DD + col);
        acc[nt][0] += x0.x; acc[nt][1] += x0.y;
        acc[nt][2] += x1.x; acc[nt][3] += x1.y;
        sum0 += acc[nt][0] + acc[nt][1];
        sq0  += acc[nt][0] * acc[nt][0] + acc[nt][1] * acc[nt][1];
        sum1 += acc[nt][2] + acc[nt][3];
        sq1  += acc[nt][2] * acc[nt][2] + acc[nt][3] * acc[nt][3];
    }
    // quad reduce over c (lanes r*4+c)
#pragma unroll
    for (int o = 1; o < 4; o <<= 1) {
        sum0 += __shfl_xor_sync(0xffffffffu, sum0, o);
        sq0  += __shfl_xor_sync(0xffffffffu, sq0,  o);
        sum1 += __shfl_xor_sync(0xffffffffu, sum1, o);
        sq1  += __shfl_xor_sync(0xffffffffu, sq1,  o);
    }
    if (c == 0) {
        s_red[(lr0 * 2 + half) * 2 + 0] = sum0;
        s_red[(lr0 * 2 + half) * 2 + 1] = sq0;
        s_red[(lr1 * 2 + half) * 2 + 0] = sum1;
        s_red[(lr1 * 2 + half) * 2 + 1] = sq1;
    }
    __syncthreads();
    float ts0 = s_red[(lr0 * 2 + 0) * 2 + 0] + s_red[(lr0 * 2 + 1) * 2 + 0];
    float tq0 = s_red[(lr0 * 2 + 0) * 2 + 1] + s_red[(lr0 * 2 + 1) * 2 + 1];
    float ts1 = s_red[(lr1 * 2 + 0) * 2 + 0] + s_red[(lr1 * 2 + 1) * 2 + 0];
    float tq1 = s_red[(lr1 * 2 + 0) * 2 + 1] + s_red[(lr1 * 2 + 1) * 2 + 1];
    float mu0 = ts0 * (1.f / 128.f);
    float mu1 = ts1 * (1.f / 128.f);
    float rs0 = rsqrtf(tq0 * (1.f / 128.f) - mu0 * mu0 + 1e-5f);
    float rs1 = rsqrtf(tq1 * (1.f / 128.f) - mu1 * mu1 + 1e-5f);
#pragma unroll
    for (int nt = 0; nt < 8; nt++) {
        int col = nc0 + nt * 8 + 2 * c;
        if (row0 < NN)
            *(float2*)(out + (size_t)row0 * DD + col) =
                make_float2((acc[nt][0] - mu0) * rs0, (acc[nt][1] - mu0) * rs0);
        if (row1 < NN)
            *(float2*)(out + (size_t)row1 * DD + col) =
                make_float2((acc[nt][2] - mu1) * rs1, (acc[nt][3] - mu1) * rs1);
    }
}

extern "C" void kernel_launch(void* const* d_in, const int* in_sizes, int n_in,
                              void* d_out, int out_size)
{
    const float* nf        = (const float*)d_in[0];
    const float* edge_attr = (const float*)d_in[1];
    const float* edge_sh   = (const float*)d_in[2];
    const float* W_node    = (const float*)d_in[3];
    const float* fc1 = (const float*)d_in[4];
    const float* b1  = (const float*)d_in[5];
    const float* fc2 = (const float*)d_in[6];
    const float* b2  = (const float*)d_in[7];
    const float* fc3 = (const float*)d_in[8];
    const float* b3  = (const float*)d_in[9];
    const float* W_sh = (const float*)d_in[10];
    const float* aW1 = (const float*)d_in[11];
    const float* ab1 = (const float*)d_in[12];
    const float* aW2 = (const float*)d_in[13];
    const float* ab2 = (const float*)d_in[14];
    const float* aW3 = (const float*)d_in[15];
    const float* ab3 = (const float*)d_in[16];
    const float* W_out = (const float*)d_in[17];
    const int* edge_index = (const int*)d_in[18];
    float* out = (float*)d_out;

    const int SMEM_NP   = 47616;
    const int SMEM_ATT  = 52288;
    const int SMEM_MSG  = 54048;
    const int SMEM_NODE = 48640;
    cudaFuncSetAttribute(k_nodeproj, cudaFuncAttributeMaxDynamicSharedMemorySize, SMEM_NP);
    cudaFuncSetAttribute(k_att,  cudaFuncAttributeMaxDynamicSharedMemorySize, SMEM_ATT);
    cudaFuncSetAttribute(k_msg,  cudaFuncAttributeMaxDynamicSharedMemorySize, SMEM_MSG);
    cudaFuncSetAttribute(k_node, cudaFuncAttributeMaxDynamicSharedMemorySize, SMEM_NODE);

    k_prep<<<152, 256>>>(W_node, fc1, fc2, fc3, W_sh, aW1, aW2, aW3, W_out);
    k_init<<<2048, 256>>>();
    k_nodeproj<<<(NN + 63) / 64, 256, SMEM_NP>>>(nf);
    k_att<<<EE / TE, 128, SMEM_ATT>>>(edge_attr, ab1, ab2, ab3, edge_index);
    k_msg<<<EE / TE, 128, SMEM_MSG>>>(edge_attr, edge_sh, b1, b2, b3, edge_index);
    k_node<<<(NN + 63) / 64, 256, SMEM_NODE>>>(nf, out);
}